// round 12
// baseline (speedup 1.0000x reference)
#include <cuda_runtime.h>
#include <cuda_fp16.h>
#include <cstdint>

#define NPIX (4 * 256 * 256)   // 262144 pixels
#define CDIM 192
#define SCALE 0.17677669529663689f

// ---------------- scratch (static device arrays; no runtime allocs) --------
__device__ __half g_xh [NPIX * CDIM];
__device__ __half g_q  [NPIX * CDIM];
__device__ __half g_k  [NPIX * CDIM];
__device__ __half g_v  [NPIX * CDIM];
__device__ __half g_ao [NPIX * CDIM];
__device__ __half g_t3a[NPIX * 32];
__device__ __half g_t3b[NPIX * 32];
__device__ __half g_t5a[NPIX * 16];
__device__ __half g_t5b[NPIX * 16];
__device__ __half g_wh [319744];       // packed fp16 weights (incl. proj)

__device__ __forceinline__ uint32_t pack_h2(float a, float b) {
    __half2 h = __floats2half2_rn(a, b);
    return *(uint32_t*)&h;
}
__device__ __forceinline__ uint32_t smem_u32(const void* p) {
    uint32_t a;
    asm("{ .reg .u64 t; cvta.to.shared.u64 t, %1; cvt.u32.u64 %0, t; }"
        : "=r"(a) : "l"(p));
    return a;
}
__device__ __forceinline__ void cpa16(uint32_t dst, const void* src, int nbytes) {
    asm volatile("cp.async.cg.shared.global [%0], [%1], 16, %2;"
                 :: "r"(dst), "l"(src), "r"(nbytes));
}
__device__ __forceinline__ void cpa_commit() {
    asm volatile("cp.async.commit_group;" ::: "memory");
}
template <int N>
__device__ __forceinline__ void cpa_wait() {
    asm volatile("cp.async.wait_group %0;" :: "n"(N) : "memory");
}
__device__ __forceinline__ void mma_f16_16x8x16(float* c, const uint32_t* a,
                                                const uint32_t* b) {
    asm volatile(
        "mma.sync.aligned.m16n8k16.row.col.f32.f16.f16.f32 "
        "{%0,%1,%2,%3}, {%4,%5,%6,%7}, {%8,%9}, {%0,%1,%2,%3};"
        : "+f"(c[0]), "+f"(c[1]), "+f"(c[2]), "+f"(c[3])
        : "r"(a[0]), "r"(a[1]), "r"(a[2]), "r"(a[3]), "r"(b[0]), "r"(b[1]));
}
#define LDSM4(r0, r1, r2, r3, addr)                                           \
    asm volatile("ldmatrix.sync.aligned.m8n8.x4.shared.b16 {%0,%1,%2,%3}, [%4];" \
                 : "=r"(r0), "=r"(r1), "=r"(r2), "=r"(r3) : "r"(addr))
#define LDSM2(r0, r1, addr)                                                   \
    asm volatile("ldmatrix.sync.aligned.m8n8.x2.shared.b16 {%0,%1}, [%2];"    \
                 : "=r"(r0), "=r"(r1) : "r"(addr))
#define LDSM2T(r0, r1, addr)                                                  \
    asm volatile("ldmatrix.sync.aligned.m8n8.x2.trans.shared.b16 {%0,%1}, [%2];" \
                 : "=r"(r0), "=r"(r1) : "r"(addr))

// ---------------- prepasses -------------------------------------------------
__global__ __launch_bounds__(256)
void f2h_kernel(const float* __restrict__ in, __half* __restrict__ out)
{
    int i = blockIdx.x * blockDim.x + threadIdx.x;   // one uint4 (8 halves)
    float4 a = ((const float4*)in)[2 * i];
    float4 b = ((const float4*)in)[2 * i + 1];
    uint4 o;
    o.x = pack_h2(a.x, a.y); o.y = pack_h2(a.z, a.w);
    o.z = pack_h2(b.x, b.y); o.w = pack_h2(b.z, b.w);
    ((uint4*)out)[i] = o;
}

// Pack ALL OIHW fp32 weights -> fp16 [kh][cc][kw][cout][16ch] in one launch.
struct PackSrc { const float* p[9]; };
__global__ __launch_bounds__(256)
void pack_all(PackSrc ps, __half* __restrict__ dst)
{
    const int KSt[9]  = {1, 1, 3, 1, 3, 5, 1, 5, 1};
    const int CINt[9] = {192, 192, 192, 32, 32, 192, 16, 16, 192};
    const int COUTt[9]= {192, 128, 32, 32, 128, 16, 16, 128, 192};
    const int TOTt[9] = {36864, 24576, 55296, 1024, 36864, 76800, 256, 51200, 36864};
    int idx = blockIdx.x * 256 + threadIdx.x;
    if (idx >= 319744) return;
    int w = 0, local = idx;
    while (local >= TOTt[w]) { local -= TOTt[w]; w++; }
    const int KS = KSt[w], CIN = CINt[w], COUT = COUTt[w];
    int ci = local & 15;
    int t = local >> 4;
    int cout = t % COUT; t /= COUT;
    int kw = t % KS; t /= KS;
    int cc = t % (CIN / 16); t /= (CIN / 16);
    int kh = t;
    dst[idx] = __float2half(
        ps.p[w][((size_t)(cout * CIN + cc * 16 + ci) * KS + kh) * KS + kw]);
}

// ============================================================================
// Implicit-GEMM conv: fp16 mma.sync, cp.async staging, ldmatrix fragments.
// One CTA = 128 output pixels (half an image row) x BN output channels.
// MI=2 per warp -> 32 accumulator regs -> 3-8 CTAs/SM.
// grid = (2048 half-rows, CT/BN).
// ============================================================================
template <int KS, int CIN, int CT, int BN, int OSTR, bool RELU, bool SPLIT,
          typename OutT, int NT>
__global__ __launch_bounds__(NT)
void conv_mma(const __half* __restrict__ X, const __half* __restrict__ Wp,
              const float* __restrict__ bias, OutT* __restrict__ out0,
              OutT* __restrict__ out1, int cbase)
{
    constexpr int PAD = KS / 2;
    constexpr int NCH = CIN / 16;
    constexpr int NSTAGE = KS * NCH;
    constexpr int SLAB = 128 + 2 * PAD;
    constexpr int ABYTES = SLAB * 48;
    constexpr int BBYTES = KS * BN * 48;
    constexpr int BUFB = ABYTES + BBYTES;
    __shared__ alignas(16) char smem[2 * BUFB];

    const int tid = threadIdx.x;
    const int lane = tid & 31, warp = tid >> 5;
    const int grp = lane >> 2, thr4 = lane & 3;

    constexpr int NWARPS = NT / 32;
    constexpr int NW = (BN == 64) ? 2 : 1;
    constexpr int MW = NWARPS / NW;          // 4
    constexpr int WROWS = 128 / MW;          // 32
    constexpr int WCOLS = BN / NW;
    constexpr int MI = WROWS / 16;           // 2
    constexpr int NI = WCOLS / 8;            // 4 or 2
    const int mo = (NW == 2 ? (warp >> 1) : warp) * WROWS;
    const int no = (NW == 2 ? (warp & 1) : 0) * WCOLS;

    const int pix0 = blockIdx.x << 7;        // 128-pixel tile
    const int row = pix0 >> 8;               // b*256 + h
    const int h = row & 255;
    const int w0 = pix0 & 255;               // 0 or 128
    const int n0 = blockIdx.y * BN;
    const uint32_t smbase = smem_u32(smem);

    float acc[MI][NI][4];
#pragma unroll
    for (int i = 0; i < MI; i++)
#pragma unroll
        for (int j = 0; j < NI; j++)
#pragma unroll
            for (int r = 0; r < 4; r++) acc[i][j][r] = 0.0f;

    auto issue = [&](int s) {
        const int kh = s / NCH;
        const int cc = s - kh * NCH;
        const int c0 = cc * 16;
        const int hs = h + kh - PAD;
        const bool vh = ((unsigned)hs < 256u);
        const int spix = (row - h + hs) << 8;
        const uint32_t aoff = smbase + (s & 1) * BUFB;
        for (int i = tid; i < SLAB * 2; i += NT) {
            const int p = i >> 1, hi = i & 1;
            const int ws = w0 + p - PAD;
            const bool ok = vh && ((unsigned)ws < 256u);
            const __half* src = ok
                ? X + ((size_t)(spix + ws) * CIN + c0 + hi * 8) : X;
            cpa16(aoff + p * 48 + hi * 16, src, ok ? 16 : 0);
        }
        const uint32_t boff = aoff + ABYTES;
        const __half* wb = Wp + (size_t)(kh * NCH + cc) * KS * CT * 16;
        for (int i = tid; i < KS * BN * 2; i += NT) {
            const int r = i >> 1, hi = i & 1;
            const int kw = r / BN, j = r - kw * BN;
            cpa16(boff + r * 48 + hi * 16,
                  wb + ((size_t)kw * CT + n0 + j) * 16 + hi * 8, 16);
        }
        cpa_commit();
    };

    auto compute = [&](int buf) {
        const uint32_t aB = smbase + buf * BUFB
                            + (lane & 15) * 48 + (lane >> 4) * 16;
        const uint32_t bB = smbase + buf * BUFB + ABYTES
                            + (lane & 7) * 48 + ((lane >> 3) & 1) * 16;
#pragma unroll
        for (int kw = 0; kw < KS; kw++) {
            uint32_t a[MI][4], b[NI][2];
#pragma unroll
            for (int mi = 0; mi < MI; mi++)
                LDSM4(a[mi][0], a[mi][1], a[mi][2], a[mi][3],
                      aB + (mo + mi * 16 + kw) * 48);
#pragma unroll
            for (int ni = 0; ni < NI; ni++)
                LDSM2(b[ni][0], b[ni][1], bB + (kw * BN + no + ni * 8) * 48);
#pragma unroll
            for (int mi = 0; mi < MI; mi++)
#pragma unroll
                for (int ni = 0; ni < NI; ni++)
                    mma_f16_16x8x16(acc[mi][ni], a[mi], b[ni]);
        }
    };

    issue(0);
#pragma unroll 1
    for (int s = 0; s < NSTAGE; s++) {
        if (s + 1 < NSTAGE) { issue(s + 1); cpa_wait<1>(); }
        else                { cpa_wait<0>(); }
        __syncthreads();
        compute(s & 1);
        __syncthreads();
    }

    // ---- epilogue ----
    OutT* dst;
    int cb, stride;
    if (SPLIT) {
        if (n0 < 64) { dst = out0; cb = cbase + n0; }
        else         { dst = out1; cb = cbase + n0 - 64; }
        stride = 192;
    } else { dst = out0; cb = n0; stride = OSTR; }

#pragma unroll
    for (int mi = 0; mi < MI; mi++) {
        size_t r0 = (size_t)(pix0 + mo + mi * 16 + grp);
        size_t r1 = r0 + 8;
#pragma unroll
        for (int ni = 0; ni < NI; ni++) {
            int colL = no + ni * 8 + 2 * thr4;
            float b0 = __ldg(&bias[n0 + colL]);
            float b1 = __ldg(&bias[n0 + colL + 1]);
            float v00 = acc[mi][ni][0] + b0, v01 = acc[mi][ni][1] + b1;
            float v10 = acc[mi][ni][2] + b0, v11 = acc[mi][ni][3] + b1;
            if (RELU) {
                v00 = v00 >= 0.f ? v00 : 0.2f * v00;
                v01 = v01 >= 0.f ? v01 : 0.2f * v01;
                v10 = v10 >= 0.f ? v10 : 0.2f * v10;
                v11 = v11 >= 0.f ? v11 : 0.2f * v11;
            }
            if (sizeof(OutT) == 2) {
                *(uint32_t*)&dst[r0 * stride + cb + colL] = pack_h2(v00, v01);
                *(uint32_t*)&dst[r1 * stride + cb + colL] = pack_h2(v10, v11);
            } else {
                *(float2*)&dst[r0 * stride + cb + colL] = make_float2(v00, v01);
                *(float2*)&dst[r1 * stride + cb + colL] = make_float2(v10, v11);
            }
        }
    }
}

// ============================================================================
// Window attention on mma.sync (unchanged from R11).
// ============================================================================
__global__ __launch_bounds__(64)
void attn_kernel(const __half* __restrict__ q, const __half* __restrict__ k,
                 const __half* __restrict__ v, const float* __restrict__ rpb,
                 __half* __restrict__ out)
{
    __shared__ __half Qs[64][40], Ks[64][40], Vs[64][40];
    __shared__ float rs[225];

    const int hh = blockIdx.x;
    const int wi = blockIdx.y;
    const int tid = threadIdx.x;
    const int lane = tid & 31, warp = tid >> 5;
    const int grp = lane >> 2, thr4 = lane & 3;
    const int b = wi >> 10, rem = wi & 1023;
    const int wh = rem >> 5, ww = rem & 31;
    const int r1 = tid >> 3, c1 = tid & 7;
    const int gh = wh * 8 + r1, gw = ww * 8 + c1;
    const size_t pix = (size_t)(b * 256 + gh) * 256 + gw;
    const int cb = hh * 32;

    for (int i = tid; i < 225; i += 64) rs[i] = rpb[i * 6 + hh];
    {
        const __half* qp = q + pix * 192 + cb;
        const __half* kp = k + pix * 192 + cb;
        const __half* vp = v + pix * 192 + cb;
#pragma unroll
        for (int j = 0; j < 4; j++) {
            *(uint4*)&Qs[tid][j * 8] = *(const uint4*)(qp + j * 8);
            *(uint4*)&Ks[tid][j * 8] = *(const uint4*)(kp + j * 8);
            *(uint4*)&Vs[tid][j * 8] = *(const uint4*)(vp + j * 8);
        }
    }
    __syncthreads();

    const uint32_t qb = smem_u32(&Qs[0][0]) + (lane & 15) * 80 + (lane >> 4) * 16;
    const uint32_t kb = smem_u32(&Ks[0][0]) + (lane & 7) * 80 + ((lane >> 3) & 1) * 16;
    const uint32_t vb = smem_u32(&Vs[0][0]) + (lane & 15) * 80;
    const int mo = warp * 32;

    // ---- S = Q K^T ----
    float sv[2][8][4];
#pragma unroll
    for (int mi = 0; mi < 2; mi++)
#pragma unroll
        for (int ni = 0; ni < 8; ni++)
#pragma unroll
            for (int r = 0; r < 4; r++) sv[mi][ni][r] = 0.0f;
#pragma unroll
    for (int kt = 0; kt < 2; kt++) {
        uint32_t a[2][4], bf[8][2];
#pragma unroll
        for (int mi = 0; mi < 2; mi++)
            LDSM4(a[mi][0], a[mi][1], a[mi][2], a[mi][3],
                  qb + (mo + mi * 16) * 80 + kt * 32);
#pragma unroll
        for (int ni = 0; ni < 8; ni++)
            LDSM2(bf[ni][0], bf[ni][1], kb + ni * 8 * 80 + kt * 32);
#pragma unroll
        for (int mi = 0; mi < 2; mi++)
#pragma unroll
            for (int ni = 0; ni < 8; ni++)
                mma_f16_16x8x16(sv[mi][ni], a[mi], bf[ni]);
    }

    // ---- scale + relative position bias ----
#pragma unroll
    for (int mi = 0; mi < 2; mi++)
#pragma unroll
        for (int ni = 0; ni < 8; ni++)
#pragma unroll
            for (int r = 0; r < 4; r++) {
                int rown = mo + mi * 16 + grp + (r >> 1) * 8;
                int colm = ni * 8 + thr4 * 2 + (r & 1);
                int dr = (rown >> 3) - (colm >> 3) + 7;
                int dc = (rown & 7) - (colm & 7) + 7;
                sv[mi][ni][r] = sv[mi][ni][r] * SCALE + rs[dr * 15 + dc];
            }

    // ---- softmax (rows shared across thr4 quads) ----
    float inv[2][2];
#pragma unroll
    for (int mi = 0; mi < 2; mi++)
#pragma unroll
        for (int hrow = 0; hrow < 2; hrow++) {
            float mx = -1e30f;
#pragma unroll
            for (int ni = 0; ni < 8; ni++) {
                mx = fmaxf(mx, sv[mi][ni][hrow * 2]);
                mx = fmaxf(mx, sv[mi][ni][hrow * 2 + 1]);
            }
            mx = fmaxf(mx, __shfl_xor_sync(0xffffffffu, mx, 1));
            mx = fmaxf(mx, __shfl_xor_sync(0xffffffffu, mx, 2));
            float sum = 0.f;
#pragma unroll
            for (int ni = 0; ni < 8; ni++) {
                float e0 = __expf(sv[mi][ni][hrow * 2] - mx);
                float e1 = __expf(sv[mi][ni][hrow * 2 + 1] - mx);
                sv[mi][ni][hrow * 2] = e0;
                sv[mi][ni][hrow * 2 + 1] = e1;
                sum += e0 + e1;
            }
            sum += __shfl_xor_sync(0xffffffffu, sum, 1);
            sum += __shfl_xor_sync(0xffffffffu, sum, 2);
            inv[mi][hrow] = 1.0f / sum;
        }

    // ---- repack P (fp16) as A fragments ----
    uint32_t pa[2][4][4];
#pragma unroll
    for (int mi = 0; mi < 2; mi++)
#pragma unroll
        for (int kt = 0; kt < 4; kt++) {
            pa[mi][kt][0] = pack_h2(sv[mi][2 * kt][0],     sv[mi][2 * kt][1]);
            pa[mi][kt][1] = pack_h2(sv[mi][2 * kt][2],     sv[mi][2 * kt][3]);
            pa[mi][kt][2] = pack_h2(sv[mi][2 * kt + 1][0], sv[mi][2 * kt + 1][1]);
            pa[mi][kt][3] = pack_h2(sv[mi][2 * kt + 1][2], sv[mi][2 * kt + 1][3]);
        }

    // ---- O = P V ----
    float ov[2][4][4];
#pragma unroll
    for (int mi = 0; mi < 2; mi++)
#pragma unroll
        for (int ni = 0; ni < 4; ni++)
#pragma unroll
            for (int r = 0; r < 4; r++) ov[mi][ni][r] = 0.0f;
#pragma unroll
    for (int kt = 0; kt < 4; kt++) {
        uint32_t bv[4][2];
#pragma unroll
        for (int ni = 0; ni < 4; ni++)
            LDSM2T(bv[ni][0], bv[ni][1], vb + kt * 16 * 80 + ni * 16);
#pragma unroll
        for (int mi = 0; mi < 2; mi++)
#pragma unroll
            for (int ni = 0; ni < 4; ni++)
                mma_f16_16x8x16(ov[mi][ni], pa[mi][kt], bv[ni]);
    }

    // ---- normalize + store (window-ordered pixels) ----
#pragma unroll
    for (int mi = 0; mi < 2; mi++) {
        int rown = mo + mi * 16 + grp;
        size_t o0 = ((size_t)wi * 64 + rown) * 192 + cb + thr4 * 2;
        size_t o1 = o0 + (size_t)8 * 192;
#pragma unroll
        for (int ni = 0; ni < 4; ni++) {
            *(uint32_t*)&out[o0 + ni * 8] =
                pack_h2(ov[mi][ni][0] * inv[mi][0], ov[mi][ni][1] * inv[mi][0]);
            *(uint32_t*)&out[o1 + ni * 8] =
                pack_h2(ov[mi][ni][2] * inv[mi][1], ov[mi][ni][3] * inv[mi][1]);
        }
    }
}

// ============================================================================
extern "C" void kernel_launch(void* const* d_in, const int* in_sizes, int n_in,
                              void* d_out, int out_size)
{
    const float* x      = (const float*)d_in[0];
    const float* v_w    = (const float*)d_in[1];
    const float* v_b    = (const float*)d_in[2];
    const float* qk1_w  = (const float*)d_in[3];
    const float* qk1_b  = (const float*)d_in[4];
    const float* qk3_w1 = (const float*)d_in[5];
    const float* qk3_b1 = (const float*)d_in[6];
    const float* qk3_w2 = (const float*)d_in[7];
    const float* qk3_b2 = (const float*)d_in[8];
    const float* qk3_w3 = (const float*)d_in[9];
    const float* qk3_b3 = (const float*)d_in[10];
    const float* qk5_w1 = (const float*)d_in[11];
    const float* qk5_b1 = (const float*)d_in[12];
    const float* qk5_w2 = (const float*)d_in[13];
    const float* qk5_b2 = (const float*)d_in[14];
    const float* qk5_w3 = (const float*)d_in[15];
    const float* qk5_b3 = (const float*)d_in[16];
    const float* rpb    = (const float*)d_in[17];
    const float* proj_w = (const float*)d_in[18];
    const float* proj_b = (const float*)d_in[19];
    float* out = (float*)d_out;

    __half *xh, *q, *k, *v, *ao, *t3a, *t3b, *t5a, *t5b, *wh;
    cudaGetSymbolAddress((void**)&xh,  g_xh);
    cudaGetSymbolAddress((void**)&q,   g_q);
    cudaGetSymbolAddress((void**)&k,   g_k);
    cudaGetSymbolAddress((void**)&v,   g_v);
    cudaGetSymbolAddress((void**)&ao,  g_ao);
    cudaGetSymbolAddress((void**)&t3a, g_t3a);
    cudaGetSymbolAddress((void**)&t3b, g_t3b);
    cudaGetSymbolAddress((void**)&t5a, g_t5a);
    cudaGetSymbolAddress((void**)&t5b, g_t5b);
    cudaGetSymbolAddress((void**)&wh,  g_wh);

    // packed weight offsets (halves), order matches pack_all tables
    const int O_V = 0, O_Q1 = 36864, O_3W1 = 61440, O_3W2 = 116736,
              O_3W3 = 117760, O_5W1 = 154624, O_5W2 = 231424, O_5W3 = 231680,
              O_PJ = 282880;

    // prepasses
    f2h_kernel<<<NPIX * CDIM / (256 * 8), 256>>>(x, xh);
    PackSrc ps;
    ps.p[0] = v_w;    ps.p[1] = qk1_w;  ps.p[2] = qk3_w1;
    ps.p[3] = qk3_w2; ps.p[4] = qk3_w3; ps.p[5] = qk5_w1;
    ps.p[6] = qk5_w2; ps.p[7] = qk5_w3; ps.p[8] = proj_w;
    pack_all<<<(319744 + 255) / 256, 256>>>(ps, wh);

    // v = conv1x1(x): N=192 in three 64-col blocks, stride 192
    conv_mma<1, 192, 192, 64, 192, false, false, __half, 256>
        <<<dim3(2048, 3), 256>>>(xh, wh + O_V, v_b, v, nullptr, 0);
    // qk1: N=128, split q/k at cbase 0
    conv_mma<1, 192, 128, 64, 192, false, true, __half, 256>
        <<<dim3(2048, 2), 256>>>(xh, wh + O_Q1, qk1_b, q, k, 0);
    // scale-3 branch
    conv_mma<3, 192, 32, 32, 32, true, false, __half, 128>
        <<<dim3(2048, 1), 128>>>(xh, wh + O_3W1, qk3_b1, t3a, nullptr, 0);
    conv_mma<1, 32, 32, 32, 32, true, false, __half, 128>
        <<<dim3(2048, 1), 128>>>(t3a, wh + O_3W2, qk3_b2, t3b, nullptr, 0);
    conv_mma<3, 32, 128, 64, 192, false, true, __half, 256>
        <<<dim3(2048, 2), 256>>>(t3b, wh + O_3W3, qk3_b3, q, k, 64);
    // scale-5 branch
    conv_mma<5, 192, 16, 16, 16, true, false, __half, 128>
        <<<dim3(2048, 1), 128>>>(xh, wh + O_5W1, qk5_b1, t5a, nullptr, 0);
    conv_mma<1, 16, 16, 16, 16, true, false, __half, 128>
        <<<dim3(2048, 1), 128>>>(t5a, wh + O_5W2, qk5_b2, t5b, nullptr, 0);
    conv_mma<5, 16, 128, 32, 192, false, true, __half, 128>
        <<<dim3(2048, 4), 128>>>(t5b, wh + O_5W3, qk5_b3, q, k, 128);
    // window attention (mma, fp16 in/out)
    attn_kernel<<<dim3(6, 4096), 64>>>(q, k, v, rpb, ao);
    // output projection straight into d_out (fp32)
    conv_mma<1, 192, 192, 64, 192, false, false, float, 256>
        <<<dim3(2048, 3), 256>>>(ao, wh + O_PJ, proj_b, out, nullptr, 0);
}

// round 14
// speedup vs baseline: 1.1581x; 1.1581x over previous
#include <cuda_runtime.h>
#include <cuda_fp16.h>
#include <cstdint>

#define NPIX (4 * 256 * 256)   // 262144 pixels
#define CDIM 192
#define SCALE 0.17677669529663689f

// ---------------- scratch (static device arrays; no runtime allocs) --------
__device__ __half g_xh [NPIX * CDIM];
__device__ __half g_q  [NPIX * CDIM];
__device__ __half g_k  [NPIX * CDIM];
__device__ __half g_v  [NPIX * CDIM];
__device__ __half g_ao [NPIX * CDIM];
__device__ __half g_t3a[NPIX * 32];
__device__ __half g_t3b[NPIX * 32];
__device__ __half g_t5a[NPIX * 16];
__device__ __half g_t5b[NPIX * 16];
__device__ __half g_wh [319744];       // packed fp16 weights (incl. proj)

__device__ __forceinline__ uint32_t pack_h2(float a, float b) {
    __half2 h = __floats2half2_rn(a, b);
    return *(uint32_t*)&h;
}
__device__ __forceinline__ uint32_t smem_u32(const void* p) {
    uint32_t a;
    asm("{ .reg .u64 t; cvta.to.shared.u64 t, %1; cvt.u32.u64 %0, t; }"
        : "=r"(a) : "l"(p));
    return a;
}
__device__ __forceinline__ void cpa16(uint32_t dst, const void* src, int nbytes) {
    asm volatile("cp.async.cg.shared.global [%0], [%1], 16, %2;"
                 :: "r"(dst), "l"(src), "r"(nbytes));
}
__device__ __forceinline__ void cpa_commit() {
    asm volatile("cp.async.commit_group;" ::: "memory");
}
template <int N>
__device__ __forceinline__ void cpa_wait() {
    asm volatile("cp.async.wait_group %0;" :: "n"(N) : "memory");
}
__device__ __forceinline__ void mma_f16_16x8x16(float* c, const uint32_t* a,
                                                const uint32_t* b) {
    asm volatile(
        "mma.sync.aligned.m16n8k16.row.col.f32.f16.f16.f32 "
        "{%0,%1,%2,%3}, {%4,%5,%6,%7}, {%8,%9}, {%0,%1,%2,%3};"
        : "+f"(c[0]), "+f"(c[1]), "+f"(c[2]), "+f"(c[3])
        : "r"(a[0]), "r"(a[1]), "r"(a[2]), "r"(a[3]), "r"(b[0]), "r"(b[1]));
}
#define LDSM4(r0, r1, r2, r3, addr)                                           \
    asm volatile("ldmatrix.sync.aligned.m8n8.x4.shared.b16 {%0,%1,%2,%3}, [%4];" \
                 : "=r"(r0), "=r"(r1), "=r"(r2), "=r"(r3) : "r"(addr))
#define LDSM2(r0, r1, addr)                                                   \
    asm volatile("ldmatrix.sync.aligned.m8n8.x2.shared.b16 {%0,%1}, [%2];"    \
                 : "=r"(r0), "=r"(r1) : "r"(addr))
#define LDSM2T(r0, r1, addr)                                                  \
    asm volatile("ldmatrix.sync.aligned.m8n8.x2.trans.shared.b16 {%0,%1}, [%2];" \
                 : "=r"(r0), "=r"(r1) : "r"(addr))

// ---------------- prepasses -------------------------------------------------
__global__ __launch_bounds__(256)
void f2h_kernel(const float* __restrict__ in, __half* __restrict__ out)
{
    int i = blockIdx.x * blockDim.x + threadIdx.x;   // one uint4 (8 halves)
    float4 a = ((const float4*)in)[2 * i];
    float4 b = ((const float4*)in)[2 * i + 1];
    uint4 o;
    o.x = pack_h2(a.x, a.y); o.y = pack_h2(a.z, a.w);
    o.z = pack_h2(b.x, b.y); o.w = pack_h2(b.z, b.w);
    ((uint4*)out)[i] = o;
}

// Pack ALL OIHW fp32 weights -> fp16 [kh][cc][kw][cout][16ch] in one launch.
struct PackSrc { const float* p[9]; };
__global__ __launch_bounds__(256)
void pack_all(PackSrc ps, __half* __restrict__ dst)
{
    const int KSt[9]  = {1, 1, 3, 1, 3, 5, 1, 5, 1};
    const int CINt[9] = {192, 192, 192, 32, 32, 192, 16, 16, 192};
    const int COUTt[9]= {192, 128, 32, 32, 128, 16, 16, 128, 192};
    const int TOTt[9] = {36864, 24576, 55296, 1024, 36864, 76800, 256, 51200, 36864};
    int idx = blockIdx.x * 256 + threadIdx.x;
    if (idx >= 319744) return;
    int w = 0, local = idx;
    while (local >= TOTt[w]) { local -= TOTt[w]; w++; }
    const int KS = KSt[w], CIN = CINt[w], COUT = COUTt[w];
    int ci = local & 15;
    int t = local >> 4;
    int cout = t % COUT; t /= COUT;
    int kw = t % KS; t /= KS;
    int cc = t % (CIN / 16); t /= (CIN / 16);
    int kh = t;
    dst[idx] = __float2half(
        ps.p[w][((size_t)(cout * CIN + cc * 16 + ci) * KS + kh) * KS + kw]);
}

// ============================================================================
// gemm1: 1x1 conv with CIN=192, A tile fully SMEM-resident.
// One CTA = 256 pixels (one image row, contiguous 96KB in NHWC) x NBLK
// n-blocks of 64 couts processed sequentially (A staged ONCE). B chunks
// (64 couts x 16 ch = 2KB) double-buffered per K-step, L2-hot.
// 256 threads / 8 warps (2x4); per n-block MI=4 x NI=4 (64 acc regs, reused).
// grid = 1024. SMEM = 256*400 + 2*3072 = 108544 B (dynamic).
// ============================================================================
#define G1_AS 400                      // A row stride bytes (100 words, %32==4)
#define G1_AB (256 * G1_AS)            // 102400
#define G1_BB 3072                     // one B buffer (64 couts * 48B)

template <int NBLK, int CT, bool SPLIT, typename OutT>
__global__ __launch_bounds__(256)
void gemm1(const __half* __restrict__ X, const __half* __restrict__ Wp,
           const float* __restrict__ bias, OutT* __restrict__ out0,
           OutT* __restrict__ out1)
{
    extern __shared__ __align__(16) char smem[];
    const int tid = threadIdx.x;
    const int lane = tid & 31, warp = tid >> 5;
    const int grp = lane >> 2, thr4 = lane & 3;
    const int mo = (warp >> 1) * 64;         // warp M offset (MI=4 -> 64 rows)
    const int no = (warp & 1) * 32;          // warp N offset (NI=4 -> 32 cols)
    const int pix0 = blockIdx.x << 8;        // full image row
    const uint32_t smbase = smem_u32(smem);

    // ---- stage A: 96KB contiguous -> [pixel][192ch] rows, stride 400B ----
#pragma unroll
    for (int r = 0; r < 24; r++) {
        const int i = tid + r * 256;         // 0..6143 16B-chunks
        const int pixel = i / 24, ch = i - pixel * 24;
        cpa16(smbase + pixel * G1_AS + ch * 16,
              X + (size_t)pix0 * 192 + (size_t)i * 8, 16);
    }
    cpa_commit();

    auto issueB = [&](int nb, int c, int buf) {
        if (tid < 128) {
            const int j = tid >> 1, hi = tid & 1;
            cpa16(smbase + G1_AB + buf * G1_BB + j * 48 + hi * 16,
                  Wp + (size_t)c * (CT * 16) + (nb * 64 + j) * 16 + hi * 8, 16);
        }
        cpa_commit();
    };

    issueB(0, 0, 0);
    cpa_wait<0>();
    __syncthreads();

    const uint32_t aF = smbase + (lane & 15) * G1_AS + (lane >> 4) * 16;
    const uint32_t bF = smbase + G1_AB + (lane & 7) * 48 + ((lane >> 3) & 1) * 16;

    int buf = 0;
#pragma unroll 1
    for (int nb = 0; nb < NBLK; nb++) {
        float acc[4][4][4];
#pragma unroll
        for (int i = 0; i < 4; i++)
#pragma unroll
            for (int j = 0; j < 4; j++)
#pragma unroll
                for (int r = 0; r < 4; r++) acc[i][j][r] = 0.0f;

#pragma unroll 1
        for (int c = 0; c < 12; c++) {
            // prefetch next B chunk into the other buffer
            int cn = c + 1, nbn = nb;
            if (cn == 12) { cn = 0; nbn = nb + 1; }
            if (nbn < NBLK) issueB(nbn, cn, buf ^ 1);
            else cpa_commit();

            // compute chunk c from resident A + current B buffer
            uint32_t a[4][4], b[4][2];
#pragma unroll
            for (int mi = 0; mi < 4; mi++)
                LDSM4(a[mi][0], a[mi][1], a[mi][2], a[mi][3],
                      aF + (mo + mi * 16) * G1_AS + c * 32);
#pragma unroll
            for (int ni = 0; ni < 4; ni++)
                LDSM2(b[ni][0], b[ni][1],
                      bF + buf * G1_BB + (no + ni * 8) * 48);
#pragma unroll
            for (int mi = 0; mi < 4; mi++)
#pragma unroll
                for (int ni = 0; ni < 4; ni++)
                    mma_f16_16x8x16(acc[mi][ni], a[mi], b[ni]);

            cpa_wait<0>();
            __syncthreads();
            buf ^= 1;
        }

        // ---- epilogue for this n-block ----
        const int n0 = nb * 64;
        OutT* dst;
        int cb;
        if (SPLIT) { dst = (nb == 0) ? out0 : out1; cb = 0; }
        else       { dst = out0; cb = n0; }
#pragma unroll
        for (int mi = 0; mi < 4; mi++) {
            size_t r0 = (size_t)(pix0 + mo + mi * 16 + grp);
            size_t r1 = r0 + 8;
#pragma unroll
            for (int ni = 0; ni < 4; ni++) {
                int colL = no + ni * 8 + 2 * thr4;
                float b0 = __ldg(&bias[n0 + colL]);
                float b1 = __ldg(&bias[n0 + colL + 1]);
                float v00 = acc[mi][ni][0] + b0, v01 = acc[mi][ni][1] + b1;
                float v10 = acc[mi][ni][2] + b0, v11 = acc[mi][ni][3] + b1;
                if (sizeof(OutT) == 2) {
                    *(uint32_t*)&dst[r0 * 192 + cb + colL] = pack_h2(v00, v01);
                    *(uint32_t*)&dst[r1 * 192 + cb + colL] = pack_h2(v10, v11);
                } else {
                    *(float2*)&dst[r0 * 192 + cb + colL] = make_float2(v00, v01);
                    *(float2*)&dst[r1 * 192 + cb + colL] = make_float2(v10, v11);
                }
            }
        }
    }
}

// ============================================================================
// Implicit-GEMM conv (R11 config): fp16 mma.sync, cp.async double buffer,
// ldmatrix fragments. One CTA = one image row (256 pixels) x BN couts.
// ============================================================================
template <int KS, int CIN, int CT, int BN, int OSTR, bool RELU, bool SPLIT,
          typename OutT, int NT>
__global__ __launch_bounds__(NT)
void conv_mma(const __half* __restrict__ X, const __half* __restrict__ Wp,
              const float* __restrict__ bias, OutT* __restrict__ out0,
              OutT* __restrict__ out1, int cbase)
{
    constexpr int PAD = KS / 2;
    constexpr int NCH = CIN / 16;
    constexpr int NSTAGE = KS * NCH;
    constexpr int SLAB = 256 + 2 * PAD;
    constexpr int ABYTES = SLAB * 48;
    constexpr int BBYTES = KS * BN * 48;
    constexpr int BUFB = ABYTES + BBYTES;
    __shared__ alignas(16) char smem[2 * BUFB];

    const int tid = threadIdx.x;
    const int lane = tid & 31, warp = tid >> 5;
    const int grp = lane >> 2, thr4 = lane & 3;

    constexpr int NWARPS = NT / 32;
    constexpr int NW = (BN == 64) ? 2 : 1;
    constexpr int MW = NWARPS / NW;
    constexpr int WROWS = 256 / MW;          // 64
    constexpr int WCOLS = BN / NW;
    constexpr int MI = WROWS / 16;           // 4
    constexpr int NI = WCOLS / 8;
    static_assert(MI == 4, "tiling");
    const int mo = (NW == 2 ? (warp >> 1) : warp) * WROWS;
    const int no = (NW == 2 ? (warp & 1) : 0) * WCOLS;

    const int row = blockIdx.x;              // b*256 + h
    const int h = row & 255;
    const int pixbase = row << 8;
    const int n0 = blockIdx.y * BN;
    const uint32_t smbase = smem_u32(smem);

    float acc[MI][NI][4];
#pragma unroll
    for (int i = 0; i < MI; i++)
#pragma unroll
        for (int j = 0; j < NI; j++)
#pragma unroll
            for (int r = 0; r < 4; r++) acc[i][j][r] = 0.0f;

    auto issue = [&](int s) {
        const int kh = s / NCH;
        const int cc = s - kh * NCH;
        const int c0 = cc * 16;
        const int hs = h + kh - PAD;
        const bool vh = ((unsigned)hs < 256u);
        const int spix = (row - h + hs) << 8;
        const uint32_t aoff = smbase + (s & 1) * BUFB;
        for (int i = tid; i < SLAB * 2; i += NT) {
            const int p = i >> 1, hi = i & 1;
            const int ws = p - PAD;
            const bool ok = vh && ((unsigned)ws < 256u);
            const __half* src = ok
                ? X + ((size_t)(spix + ws) * CIN + c0 + hi * 8) : X;
            cpa16(aoff + p * 48 + hi * 16, src, ok ? 16 : 0);
        }
        const uint32_t boff = aoff + ABYTES;
        const __half* wb = Wp + (size_t)(kh * NCH + cc) * KS * CT * 16;
        for (int i = tid; i < KS * BN * 2; i += NT) {
            const int r = i >> 1, hi = i & 1;
            const int kw = r / BN, j = r - kw * BN;
            cpa16(boff + r * 48 + hi * 16,
                  wb + ((size_t)kw * CT + n0 + j) * 16 + hi * 8, 16);
        }
        cpa_commit();
    };

    auto compute = [&](int buf) {
        const uint32_t aB = smbase + buf * BUFB
                            + (lane & 15) * 48 + (lane >> 4) * 16;
        const uint32_t bB = smbase + buf * BUFB + ABYTES
                            + (lane & 7) * 48 + ((lane >> 3) & 1) * 16;
#pragma unroll
        for (int kw = 0; kw < KS; kw++) {
            uint32_t a[MI][4], b[NI][2];
#pragma unroll
            for (int mi = 0; mi < MI; mi++)
                LDSM4(a[mi][0], a[mi][1], a[mi][2], a[mi][3],
                      aB + (mo + mi * 16 + kw) * 48);
#pragma unroll
            for (int ni = 0; ni < NI; ni++)
                LDSM2(b[ni][0], b[ni][1], bB + (kw * BN + no + ni * 8) * 48);
#pragma unroll
            for (int mi = 0; mi < MI; mi++)
#pragma unroll
                for (int ni = 0; ni < NI; ni++)
                    mma_f16_16x8x16(acc[mi][ni], a[mi], b[ni]);
        }
    };

    issue(0);
#pragma unroll 1
    for (int s = 0; s < NSTAGE; s++) {
        if (s + 1 < NSTAGE) { issue(s + 1); cpa_wait<1>(); }
        else                { cpa_wait<0>(); }
        __syncthreads();
        compute(s & 1);
        __syncthreads();
    }

    // ---- epilogue ----
    OutT* dst;
    int cb, stride;
    if (SPLIT) {
        if (n0 < 64) { dst = out0; cb = cbase + n0; }
        else         { dst = out1; cb = cbase + n0 - 64; }
        stride = 192;
    } else { dst = out0; cb = n0; stride = OSTR; }

#pragma unroll
    for (int mi = 0; mi < MI; mi++) {
        size_t r0 = (size_t)(pixbase + mo + mi * 16 + grp);
        size_t r1 = r0 + 8;
#pragma unroll
        for (int ni = 0; ni < NI; ni++) {
            int colL = no + ni * 8 + 2 * thr4;
            float b0 = __ldg(&bias[n0 + colL]);
            float b1 = __ldg(&bias[n0 + colL + 1]);
            float v00 = acc[mi][ni][0] + b0, v01 = acc[mi][ni][1] + b1;
            float v10 = acc[mi][ni][2] + b0, v11 = acc[mi][ni][3] + b1;
            if (RELU) {
                v00 = v00 >= 0.f ? v00 : 0.2f * v00;
                v01 = v01 >= 0.f ? v01 : 0.2f * v01;
                v10 = v10 >= 0.f ? v10 : 0.2f * v10;
                v11 = v11 >= 0.f ? v11 : 0.2f * v11;
            }
            if (sizeof(OutT) == 2) {
                *(uint32_t*)&dst[r0 * stride + cb + colL] = pack_h2(v00, v01);
                *(uint32_t*)&dst[r1 * stride + cb + colL] = pack_h2(v10, v11);
            } else {
                *(float2*)&dst[r0 * stride + cb + colL] = make_float2(v00, v01);
                *(float2*)&dst[r1 * stride + cb + colL] = make_float2(v10, v11);
            }
        }
    }
}

// ============================================================================
// Window attention on mma.sync (unchanged from R11).
// ============================================================================
__global__ __launch_bounds__(64)
void attn_kernel(const __half* __restrict__ q, const __half* __restrict__ k,
                 const __half* __restrict__ v, const float* __restrict__ rpb,
                 __half* __restrict__ out)
{
    __shared__ __half Qs[64][40], Ks[64][40], Vs[64][40];
    __shared__ float rs[225];

    const int hh = blockIdx.x;
    const int wi = blockIdx.y;
    const int tid = threadIdx.x;
    const int lane = tid & 31, warp = tid >> 5;
    const int grp = lane >> 2, thr4 = lane & 3;
    const int b = wi >> 10, rem = wi & 1023;
    const int wh = rem >> 5, ww = rem & 31;
    const int r1 = tid >> 3, c1 = tid & 7;
    const int gh = wh * 8 + r1, gw = ww * 8 + c1;
    const size_t pix = (size_t)(b * 256 + gh) * 256 + gw;
    const int cb = hh * 32;

    for (int i = tid; i < 225; i += 64) rs[i] = rpb[i * 6 + hh];
    {
        const __half* qp = q + pix * 192 + cb;
        const __half* kp = k + pix * 192 + cb;
        const __half* vp = v + pix * 192 + cb;
#pragma unroll
        for (int j = 0; j < 4; j++) {
            *(uint4*)&Qs[tid][j * 8] = *(const uint4*)(qp + j * 8);
            *(uint4*)&Ks[tid][j * 8] = *(const uint4*)(kp + j * 8);
            *(uint4*)&Vs[tid][j * 8] = *(const uint4*)(vp + j * 8);
        }
    }
    __syncthreads();

    const uint32_t qb = smem_u32(&Qs[0][0]) + (lane & 15) * 80 + (lane >> 4) * 16;
    const uint32_t kb = smem_u32(&Ks[0][0]) + (lane & 7) * 80 + ((lane >> 3) & 1) * 16;
    const uint32_t vb = smem_u32(&Vs[0][0]) + (lane & 15) * 80;
    const int mo = warp * 32;

    // ---- S = Q K^T ----
    float sv[2][8][4];
#pragma unroll
    for (int mi = 0; mi < 2; mi++)
#pragma unroll
        for (int ni = 0; ni < 8; ni++)
#pragma unroll
            for (int r = 0; r < 4; r++) sv[mi][ni][r] = 0.0f;
#pragma unroll
    for (int kt = 0; kt < 2; kt++) {
        uint32_t a[2][4], bf[8][2];
#pragma unroll
        for (int mi = 0; mi < 2; mi++)
            LDSM4(a[mi][0], a[mi][1], a[mi][2], a[mi][3],
                  qb + (mo + mi * 16) * 80 + kt * 32);
#pragma unroll
        for (int ni = 0; ni < 8; ni++)
            LDSM2(bf[ni][0], bf[ni][1], kb + ni * 8 * 80 + kt * 32);
#pragma unroll
        for (int mi = 0; mi < 2; mi++)
#pragma unroll
            for (int ni = 0; ni < 8; ni++)
                mma_f16_16x8x16(sv[mi][ni], a[mi], bf[ni]);
    }

    // ---- scale + relative position bias ----
#pragma unroll
    for (int mi = 0; mi < 2; mi++)
#pragma unroll
        for (int ni = 0; ni < 8; ni++)
#pragma unroll
            for (int r = 0; r < 4; r++) {
                int rown = mo + mi * 16 + grp + (r >> 1) * 8;
                int colm = ni * 8 + thr4 * 2 + (r & 1);
                int dr = (rown >> 3) - (colm >> 3) + 7;
                int dc = (rown & 7) - (colm & 7) + 7;
                sv[mi][ni][r] = sv[mi][ni][r] * SCALE + rs[dr * 15 + dc];
            }

    // ---- softmax (rows shared across thr4 quads) ----
    float inv[2][2];
#pragma unroll
    for (int mi = 0; mi < 2; mi++)
#pragma unroll
        for (int hrow = 0; hrow < 2; hrow++) {
            float mx = -1e30f;
#pragma unroll
            for (int ni = 0; ni < 8; ni++) {
                mx = fmaxf(mx, sv[mi][ni][hrow * 2]);
                mx = fmaxf(mx, sv[mi][ni][hrow * 2 + 1]);
            }
            mx = fmaxf(mx, __shfl_xor_sync(0xffffffffu, mx, 1));
            mx = fmaxf(mx, __shfl_xor_sync(0xffffffffu, mx, 2));
            float sum = 0.f;
#pragma unroll
            for (int ni = 0; ni < 8; ni++) {
                float e0 = __expf(sv[mi][ni][hrow * 2] - mx);
                float e1 = __expf(sv[mi][ni][hrow * 2 + 1] - mx);
                sv[mi][ni][hrow * 2] = e0;
                sv[mi][ni][hrow * 2 + 1] = e1;
                sum += e0 + e1;
            }
            sum += __shfl_xor_sync(0xffffffffu, sum, 1);
            sum += __shfl_xor_sync(0xffffffffu, sum, 2);
            inv[mi][hrow] = 1.0f / sum;
        }

    // ---- repack P (fp16) as A fragments ----
    uint32_t pa[2][4][4];
#pragma unroll
    for (int mi = 0; mi < 2; mi++)
#pragma unroll
        for (int kt = 0; kt < 4; kt++) {
            pa[mi][kt][0] = pack_h2(sv[mi][2 * kt][0],     sv[mi][2 * kt][1]);
            pa[mi][kt][1] = pack_h2(sv[mi][2 * kt][2],     sv[mi][2 * kt][3]);
            pa[mi][kt][2] = pack_h2(sv[mi][2 * kt + 1][0], sv[mi][2 * kt + 1][1]);
            pa[mi][kt][3] = pack_h2(sv[mi][2 * kt + 1][2], sv[mi][2 * kt + 1][3]);
        }

    // ---- O = P V ----
    float ov[2][4][4];
#pragma unroll
    for (int mi = 0; mi < 2; mi++)
#pragma unroll
        for (int ni = 0; ni < 4; ni++)
#pragma unroll
            for (int r = 0; r < 4; r++) ov[mi][ni][r] = 0.0f;
#pragma unroll
    for (int kt = 0; kt < 4; kt++) {
        uint32_t bv[4][2];
#pragma unroll
        for (int ni = 0; ni < 4; ni++)
            LDSM2T(bv[ni][0], bv[ni][1], vb + kt * 16 * 80 + ni * 16);
#pragma unroll
        for (int mi = 0; mi < 2; mi++)
#pragma unroll
            for (int ni = 0; ni < 4; ni++)
                mma_f16_16x8x16(ov[mi][ni], pa[mi][kt], bv[ni]);
    }

    // ---- normalize + store (window-ordered pixels) ----
#pragma unroll
    for (int mi = 0; mi < 2; mi++) {
        int rown = mo + mi * 16 + grp;
        size_t o0 = ((size_t)wi * 64 + rown) * 192 + cb + thr4 * 2;
        size_t o1 = o0 + (size_t)8 * 192;
#pragma unroll
        for (int ni = 0; ni < 4; ni++) {
            *(uint32_t*)&out[o0 + ni * 8] =
                pack_h2(ov[mi][ni][0] * inv[mi][0], ov[mi][ni][1] * inv[mi][0]);
            *(uint32_t*)&out[o1 + ni * 8] =
                pack_h2(ov[mi][ni][2] * inv[mi][1], ov[mi][ni][3] * inv[mi][1]);
        }
    }
}

// ============================================================================
extern "C" void kernel_launch(void* const* d_in, const int* in_sizes, int n_in,
                              void* d_out, int out_size)
{
    const float* x      = (const float*)d_in[0];
    const float* v_w    = (const float*)d_in[1];
    const float* v_b    = (const float*)d_in[2];
    const float* qk1_w  = (const float*)d_in[3];
    const float* qk1_b  = (const float*)d_in[4];
    const float* qk3_w1 = (const float*)d_in[5];
    const float* qk3_b1 = (const float*)d_in[6];
    const float* qk3_w2 = (const float*)d_in[7];
    const float* qk3_b2 = (const float*)d_in[8];
    const float* qk3_w3 = (const float*)d_in[9];
    const float* qk3_b3 = (const float*)d_in[10];
    const float* qk5_w1 = (const float*)d_in[11];
    const float* qk5_b1 = (const float*)d_in[12];
    const float* qk5_w2 = (const float*)d_in[13];
    const float* qk5_b2 = (const float*)d_in[14];
    const float* qk5_w3 = (const float*)d_in[15];
    const float* qk5_b3 = (const float*)d_in[16];
    const float* rpb    = (const float*)d_in[17];
    const float* proj_w = (const float*)d_in[18];
    const float* proj_b = (const float*)d_in[19];
    float* out = (float*)d_out;

    __half *xh, *q, *k, *v, *ao, *t3a, *t3b, *t5a, *t5b, *wh;
    cudaGetSymbolAddress((void**)&xh,  g_xh);
    cudaGetSymbolAddress((void**)&q,   g_q);
    cudaGetSymbolAddress((void**)&k,   g_k);
    cudaGetSymbolAddress((void**)&v,   g_v);
    cudaGetSymbolAddress((void**)&ao,  g_ao);
    cudaGetSymbolAddress((void**)&t3a, g_t3a);
    cudaGetSymbolAddress((void**)&t3b, g_t3b);
    cudaGetSymbolAddress((void**)&t5a, g_t5a);
    cudaGetSymbolAddress((void**)&t5b, g_t5b);
    cudaGetSymbolAddress((void**)&wh,  g_wh);

    // packed weight offsets (halves), order matches pack_all tables
    const int O_V = 0, O_Q1 = 36864, O_3W1 = 61440, O_3W2 = 116736,
              O_3W3 = 117760, O_5W1 = 154624, O_5W2 = 231424, O_5W3 = 231680,
              O_PJ = 282880;

    const int G1_SMEM = G1_AB + 2 * G1_BB;   // 108544
    cudaFuncSetAttribute(gemm1<3, 192, false, __half>,
                         cudaFuncAttributeMaxDynamicSharedMemorySize, G1_SMEM);
    cudaFuncSetAttribute(gemm1<2, 128, true, __half>,
                         cudaFuncAttributeMaxDynamicSharedMemorySize, G1_SMEM);
    cudaFuncSetAttribute(gemm1<3, 192, false, float>,
                         cudaFuncAttributeMaxDynamicSharedMemorySize, G1_SMEM);

    // prepasses
    f2h_kernel<<<NPIX * CDIM / (256 * 8), 256>>>(x, xh);
    PackSrc ps;
    ps.p[0] = v_w;    ps.p[1] = qk1_w;  ps.p[2] = qk3_w1;
    ps.p[3] = qk3_w2; ps.p[4] = qk3_w3; ps.p[5] = qk5_w1;
    ps.p[6] = qk5_w2; ps.p[7] = qk5_w3; ps.p[8] = proj_w;
    pack_all<<<(319744 + 255) / 256, 256>>>(ps, wh);

    // v = conv1x1(x): A-resident GEMM, 3 n-blocks per CTA
    gemm1<3, 192, false, __half><<<1024, 256, G1_SMEM>>>(
        xh, wh + O_V, v_b, v, nullptr);
    // qk1: A-resident GEMM, 2 n-blocks (q, k)
    gemm1<2, 128, true, __half><<<1024, 256, G1_SMEM>>>(
        xh, wh + O_Q1, qk1_b, q, k);
    // scale-3 branch
    conv_mma<3, 192, 32, 32, 32, true, false, __half, 128>
        <<<dim3(1024, 1), 128>>>(xh, wh + O_3W1, qk3_b1, t3a, nullptr, 0);
    conv_mma<1, 32, 32, 32, 32, true, false, __half, 128>
        <<<dim3(1024, 1), 128>>>(t3a, wh + O_3W2, qk3_b2, t3b, nullptr, 0);
    conv_mma<3, 32, 128, 64, 192, false, true, __half, 256>
        <<<dim3(1024, 2), 256>>>(t3b, wh + O_3W3, qk3_b3, q, k, 64);
    // scale-5 branch
    conv_mma<5, 192, 16, 16, 16, true, false, __half, 128>
        <<<dim3(1024, 1), 128>>>(xh, wh + O_5W1, qk5_b1, t5a, nullptr, 0);
    conv_mma<1, 16, 16, 16, 16, true, false, __half, 128>
        <<<dim3(1024, 1), 128>>>(t5a, wh + O_5W2, qk5_b2, t5b, nullptr, 0);
    conv_mma<5, 16, 128, 32, 192, false, true, __half, 128>
        <<<dim3(1024, 4), 128>>>(t5b, wh + O_5W3, qk5_b3, q, k, 128);
    // window attention (mma, fp16 in/out)
    attn_kernel<<<dim3(6, 4096), 64>>>(q, k, v, rpb, ao);
    // output projection: A-resident GEMM straight into d_out (fp32)
    gemm1<3, 192, false, float><<<1024, 256, G1_SMEM>>>(
        ao, wh + O_PJ, proj_b, out, nullptr);
}

// round 15
// speedup vs baseline: 1.2208x; 1.0541x over previous
#include <cuda_runtime.h>
#include <cuda_fp16.h>
#include <cstdint>

#define NPIX (4 * 256 * 256)   // 262144 pixels
#define CDIM 192
#define SCALE 0.17677669529663689f

// ---------------- scratch (static device arrays; no runtime allocs) --------
__device__ __half g_xh [NPIX * CDIM];
__device__ __half g_q  [NPIX * CDIM];
__device__ __half g_k  [NPIX * CDIM];
__device__ __half g_v  [NPIX * CDIM];
__device__ __half g_ao [NPIX * CDIM];
__device__ __half g_t3a[NPIX * 32];
__device__ __half g_t3b[NPIX * 32];
__device__ __half g_t5a[NPIX * 16];
__device__ __half g_t5b[NPIX * 16];
__device__ __half g_wh [319744];       // packed fp16 weights (incl. proj)

__device__ __forceinline__ uint32_t pack_h2(float a, float b) {
    __half2 h = __floats2half2_rn(a, b);
    return *(uint32_t*)&h;
}
__device__ __forceinline__ uint32_t smem_u32(const void* p) {
    uint32_t a;
    asm("{ .reg .u64 t; cvta.to.shared.u64 t, %1; cvt.u32.u64 %0, t; }"
        : "=r"(a) : "l"(p));
    return a;
}
__device__ __forceinline__ void cpa16(uint32_t dst, const void* src, int nbytes) {
    asm volatile("cp.async.cg.shared.global [%0], [%1], 16, %2;"
                 :: "r"(dst), "l"(src), "r"(nbytes));
}
__device__ __forceinline__ void cpa_commit() {
    asm volatile("cp.async.commit_group;" ::: "memory");
}
template <int N>
__device__ __forceinline__ void cpa_wait() {
    asm volatile("cp.async.wait_group %0;" :: "n"(N) : "memory");
}
__device__ __forceinline__ void mma_f16_16x8x16(float* c, const uint32_t* a,
                                                const uint32_t* b) {
    asm volatile(
        "mma.sync.aligned.m16n8k16.row.col.f32.f16.f16.f32 "
        "{%0,%1,%2,%3}, {%4,%5,%6,%7}, {%8,%9}, {%0,%1,%2,%3};"
        : "+f"(c[0]), "+f"(c[1]), "+f"(c[2]), "+f"(c[3])
        : "r"(a[0]), "r"(a[1]), "r"(a[2]), "r"(a[3]), "r"(b[0]), "r"(b[1]));
}
#define LDSM4(r0, r1, r2, r3, addr)                                           \
    asm volatile("ldmatrix.sync.aligned.m8n8.x4.shared.b16 {%0,%1,%2,%3}, [%4];" \
                 : "=r"(r0), "=r"(r1), "=r"(r2), "=r"(r3) : "r"(addr))
#define LDSM2(r0, r1, addr)                                                   \
    asm volatile("ldmatrix.sync.aligned.m8n8.x2.shared.b16 {%0,%1}, [%2];"    \
                 : "=r"(r0), "=r"(r1) : "r"(addr))
#define LDSM2T(r0, r1, addr)                                                  \
    asm volatile("ldmatrix.sync.aligned.m8n8.x2.trans.shared.b16 {%0,%1}, [%2];" \
                 : "=r"(r0), "=r"(r1) : "r"(addr))

// ---------------- prepasses -------------------------------------------------
__global__ __launch_bounds__(256)
void f2h_kernel(const float* __restrict__ in, __half* __restrict__ out)
{
    int i = blockIdx.x * blockDim.x + threadIdx.x;   // one uint4 (8 halves)
    float4 a = ((const float4*)in)[2 * i];
    float4 b = ((const float4*)in)[2 * i + 1];
    uint4 o;
    o.x = pack_h2(a.x, a.y); o.y = pack_h2(a.z, a.w);
    o.z = pack_h2(b.x, b.y); o.w = pack_h2(b.z, b.w);
    ((uint4*)out)[i] = o;
}

// Pack ALL OIHW fp32 weights -> fp16 [kh][cc][kw][cout][16ch] in one launch.
struct PackSrc { const float* p[9]; };
__global__ __launch_bounds__(256)
void pack_all(PackSrc ps, __half* __restrict__ dst)
{
    const int KSt[9]  = {1, 1, 3, 1, 3, 5, 1, 5, 1};
    const int CINt[9] = {192, 192, 192, 32, 32, 192, 16, 16, 192};
    const int COUTt[9]= {192, 128, 32, 32, 128, 16, 16, 128, 192};
    const int TOTt[9] = {36864, 24576, 55296, 1024, 36864, 76800, 256, 51200, 36864};
    int idx = blockIdx.x * 256 + threadIdx.x;
    if (idx >= 319744) return;
    int w = 0, local = idx;
    while (local >= TOTt[w]) { local -= TOTt[w]; w++; }
    const int KS = KSt[w], CIN = CINt[w], COUT = COUTt[w];
    int ci = local & 15;
    int t = local >> 4;
    int cout = t % COUT; t /= COUT;
    int kw = t % KS; t /= KS;
    int cc = t % (CIN / 16); t /= (CIN / 16);
    int kh = t;
    dst[idx] = __float2half(
        ps.p[w][((size_t)(cout * CIN + cc * 16 + ci) * KS + kh) * KS + kw]);
}

// ============================================================================
// gemm1: 1x1 conv with CIN=192, A tile fully SMEM-resident, 4-deep B ring.
// One CTA = 256 pixels (one image row, contiguous 96KB in NHWC) x NBLK
// n-blocks of 64 couts processed sequentially (A staged ONCE). B chunks
// (64 couts x 16 ch = 3KB) in a 4-buffer cp.async ring with 3-chunk lead.
// 256 threads / 8 warps (2x4); per n-block MI=4 x NI=4 (64 acc regs, reused).
// grid = 1024. SMEM = 256*400 + 4*3072 = 114688 B (dynamic).
// ============================================================================
#define G1_AS 400                      // A row stride bytes (100 words, %32==4)
#define G1_AB (256 * G1_AS)            // 102400
#define G1_BB 3072                     // one B buffer (64 couts * 48B)

template <int NBLK, int CT, bool SPLIT, typename OutT>
__global__ __launch_bounds__(256)
void gemm1(const __half* __restrict__ X, const __half* __restrict__ Wp,
           const float* __restrict__ bias, OutT* __restrict__ out0,
           OutT* __restrict__ out1)
{
    constexpr int NCHUNK = NBLK * 12;
    extern __shared__ __align__(16) char smem[];
    const int tid = threadIdx.x;
    const int lane = tid & 31, warp = tid >> 5;
    const int grp = lane >> 2, thr4 = lane & 3;
    const int mo = (warp >> 1) * 64;         // warp M offset (MI=4 -> 64 rows)
    const int no = (warp & 1) * 32;          // warp N offset (NI=4 -> 32 cols)
    const int pix0 = blockIdx.x << 8;        // full image row
    const uint32_t smbase = smem_u32(smem);

    // issue B loads for global chunk g into ring buffer g%4 (NO commit inside)
    auto issueB = [&](int g) {
        const int nb = g / 12, c = g - nb * 12;
        if (tid < 128) {
            const int j = tid >> 1, hi = tid & 1;
            cpa16(smbase + G1_AB + (g & 3) * G1_BB + j * 48 + hi * 16,
                  Wp + (size_t)c * (CT * 16) + (nb * 64 + j) * 16 + hi * 8, 16);
        }
    };

    // ---- prologue: A (96KB) + B0 in group 0; B1, B2 in groups 1, 2 ----
#pragma unroll
    for (int r = 0; r < 24; r++) {
        const int i = tid + r * 256;         // 0..6143 16B-chunks
        const int pixel = i / 24, ch = i - pixel * 24;
        cpa16(smbase + pixel * G1_AS + ch * 16,
              X + (size_t)pix0 * 192 + (size_t)i * 8, 16);
    }
    issueB(0);
    cpa_commit();                            // group: A + B0
    issueB(1); cpa_commit();
    if (NCHUNK > 2) issueB(2);
    cpa_commit();

    const uint32_t aF = smbase + (lane & 15) * G1_AS + (lane >> 4) * 16;
    const uint32_t bF = smbase + G1_AB + (lane & 7) * 48 + ((lane >> 3) & 1) * 16;

    float acc[4][4][4];
#pragma unroll
    for (int i = 0; i < 4; i++)
#pragma unroll
        for (int j = 0; j < 4; j++)
#pragma unroll
            for (int r = 0; r < 4; r++) acc[i][j][r] = 0.0f;

#pragma unroll 1
    for (int g = 0; g < NCHUNK; g++) {
        const int nb = g / 12, c = g - nb * 12;
        cpa_wait<2>();                       // B_g complete (B_{g+1},B_{g+2} pending)
        __syncthreads();                     // B_g visible; buffer (g-1)%4 drained
        if (g + 3 < NCHUNK) issueB(g + 3);
        cpa_commit();                        // keep group count exact
        {
            uint32_t a[4][4], b[4][2];
#pragma unroll
            for (int mi = 0; mi < 4; mi++)
                LDSM4(a[mi][0], a[mi][1], a[mi][2], a[mi][3],
                      aF + (mo + mi * 16) * G1_AS + c * 32);
#pragma unroll
            for (int ni = 0; ni < 4; ni++)
                LDSM2(b[ni][0], b[ni][1],
                      bF + (g & 3) * G1_BB + (no + ni * 8) * 48);
#pragma unroll
            for (int mi = 0; mi < 4; mi++)
#pragma unroll
                for (int ni = 0; ni < 4; ni++)
                    mma_f16_16x8x16(acc[mi][ni], a[mi], b[ni]);
        }

        if (c == 11) {
            // ---- epilogue for n-block nb, then reset accumulators ----
            const int n0 = nb * 64;
            OutT* dst;
            int cb;
            if (SPLIT) { dst = (nb == 0) ? out0 : out1; cb = 0; }
            else       { dst = out0; cb = n0; }
#pragma unroll
            for (int mi = 0; mi < 4; mi++) {
                size_t r0 = (size_t)(pix0 + mo + mi * 16 + grp);
                size_t r1 = r0 + 8;
#pragma unroll
                for (int ni = 0; ni < 4; ni++) {
                    int colL = no + ni * 8 + 2 * thr4;
                    float b0 = __ldg(&bias[n0 + colL]);
                    float b1 = __ldg(&bias[n0 + colL + 1]);
                    float v00 = acc[mi][ni][0] + b0, v01 = acc[mi][ni][1] + b1;
                    float v10 = acc[mi][ni][2] + b0, v11 = acc[mi][ni][3] + b1;
                    if (sizeof(OutT) == 2) {
                        *(uint32_t*)&dst[r0 * 192 + cb + colL] = pack_h2(v00, v01);
                        *(uint32_t*)&dst[r1 * 192 + cb + colL] = pack_h2(v10, v11);
                    } else {
                        *(float2*)&dst[r0 * 192 + cb + colL] = make_float2(v00, v01);
                        *(float2*)&dst[r1 * 192 + cb + colL] = make_float2(v10, v11);
                    }
                    acc[mi][ni][0] = 0.f; acc[mi][ni][1] = 0.f;
                    acc[mi][ni][2] = 0.f; acc[mi][ni][3] = 0.f;
                }
            }
        }
    }
}

// ============================================================================
// Implicit-GEMM conv (R11 config): fp16 mma.sync, cp.async double buffer,
// ldmatrix fragments. One CTA = one image row (256 pixels) x BN couts.
// ============================================================================
template <int KS, int CIN, int CT, int BN, int OSTR, bool RELU, bool SPLIT,
          typename OutT, int NT>
__global__ __launch_bounds__(NT)
void conv_mma(const __half* __restrict__ X, const __half* __restrict__ Wp,
              const float* __restrict__ bias, OutT* __restrict__ out0,
              OutT* __restrict__ out1, int cbase)
{
    constexpr int PAD = KS / 2;
    constexpr int NCH = CIN / 16;
    constexpr int NSTAGE = KS * NCH;
    constexpr int SLAB = 256 + 2 * PAD;
    constexpr int ABYTES = SLAB * 48;
    constexpr int BBYTES = KS * BN * 48;
    constexpr int BUFB = ABYTES + BBYTES;
    __shared__ alignas(16) char smem[2 * BUFB];

    const int tid = threadIdx.x;
    const int lane = tid & 31, warp = tid >> 5;
    const int grp = lane >> 2, thr4 = lane & 3;

    constexpr int NWARPS = NT / 32;
    constexpr int NW = (BN == 64) ? 2 : 1;
    constexpr int MW = NWARPS / NW;
    constexpr int WROWS = 256 / MW;          // 64
    constexpr int WCOLS = BN / NW;
    constexpr int MI = WROWS / 16;           // 4
    constexpr int NI = WCOLS / 8;
    static_assert(MI == 4, "tiling");
    const int mo = (NW == 2 ? (warp >> 1) : warp) * WROWS;
    const int no = (NW == 2 ? (warp & 1) : 0) * WCOLS;

    const int row = blockIdx.x;              // b*256 + h
    const int h = row & 255;
    const int pixbase = row << 8;
    const int n0 = blockIdx.y * BN;
    const uint32_t smbase = smem_u32(smem);

    float acc[MI][NI][4];
#pragma unroll
    for (int i = 0; i < MI; i++)
#pragma unroll
        for (int j = 0; j < NI; j++)
#pragma unroll
            for (int r = 0; r < 4; r++) acc[i][j][r] = 0.0f;

    auto issue = [&](int s) {
        const int kh = s / NCH;
        const int cc = s - kh * NCH;
        const int c0 = cc * 16;
        const int hs = h + kh - PAD;
        const bool vh = ((unsigned)hs < 256u);
        const int spix = (row - h + hs) << 8;
        const uint32_t aoff = smbase + (s & 1) * BUFB;
        for (int i = tid; i < SLAB * 2; i += NT) {
            const int p = i >> 1, hi = i & 1;
            const int ws = p - PAD;
            const bool ok = vh && ((unsigned)ws < 256u);
            const __half* src = ok
                ? X + ((size_t)(spix + ws) * CIN + c0 + hi * 8) : X;
            cpa16(aoff + p * 48 + hi * 16, src, ok ? 16 : 0);
        }
        const uint32_t boff = aoff + ABYTES;
        const __half* wb = Wp + (size_t)(kh * NCH + cc) * KS * CT * 16;
        for (int i = tid; i < KS * BN * 2; i += NT) {
            const int r = i >> 1, hi = i & 1;
            const int kw = r / BN, j = r - kw * BN;
            cpa16(boff + r * 48 + hi * 16,
                  wb + ((size_t)kw * CT + n0 + j) * 16 + hi * 8, 16);
        }
        cpa_commit();
    };

    auto compute = [&](int buf) {
        const uint32_t aB = smbase + buf * BUFB
                            + (lane & 15) * 48 + (lane >> 4) * 16;
        const uint32_t bB = smbase + buf * BUFB + ABYTES
                            + (lane & 7) * 48 + ((lane >> 3) & 1) * 16;
#pragma unroll
        for (int kw = 0; kw < KS; kw++) {
            uint32_t a[MI][4], b[NI][2];
#pragma unroll
            for (int mi = 0; mi < MI; mi++)
                LDSM4(a[mi][0], a[mi][1], a[mi][2], a[mi][3],
                      aB + (mo + mi * 16 + kw) * 48);
#pragma unroll
            for (int ni = 0; ni < NI; ni++)
                LDSM2(b[ni][0], b[ni][1], bB + (kw * BN + no + ni * 8) * 48);
#pragma unroll
            for (int mi = 0; mi < MI; mi++)
#pragma unroll
                for (int ni = 0; ni < NI; ni++)
                    mma_f16_16x8x16(acc[mi][ni], a[mi], b[ni]);
        }
    };

    issue(0);
#pragma unroll 1
    for (int s = 0; s < NSTAGE; s++) {
        if (s + 1 < NSTAGE) { issue(s + 1); cpa_wait<1>(); }
        else                { cpa_wait<0>(); }
        __syncthreads();
        compute(s & 1);
        __syncthreads();
    }

    // ---- epilogue ----
    OutT* dst;
    int cb, stride;
    if (SPLIT) {
        if (n0 < 64) { dst = out0; cb = cbase + n0; }
        else         { dst = out1; cb = cbase + n0 - 64; }
        stride = 192;
    } else { dst = out0; cb = n0; stride = OSTR; }

#pragma unroll
    for (int mi = 0; mi < MI; mi++) {
        size_t r0 = (size_t)(pixbase + mo + mi * 16 + grp);
        size_t r1 = r0 + 8;
#pragma unroll
        for (int ni = 0; ni < NI; ni++) {
            int colL = no + ni * 8 + 2 * thr4;
            float b0 = __ldg(&bias[n0 + colL]);
            float b1 = __ldg(&bias[n0 + colL + 1]);
            float v00 = acc[mi][ni][0] + b0, v01 = acc[mi][ni][1] + b1;
            float v10 = acc[mi][ni][2] + b0, v11 = acc[mi][ni][3] + b1;
            if (RELU) {
                v00 = v00 >= 0.f ? v00 : 0.2f * v00;
                v01 = v01 >= 0.f ? v01 : 0.2f * v01;
                v10 = v10 >= 0.f ? v10 : 0.2f * v10;
                v11 = v11 >= 0.f ? v11 : 0.2f * v11;
            }
            if (sizeof(OutT) == 2) {
                *(uint32_t*)&dst[r0 * stride + cb + colL] = pack_h2(v00, v01);
                *(uint32_t*)&dst[r1 * stride + cb + colL] = pack_h2(v10, v11);
            } else {
                *(float2*)&dst[r0 * stride + cb + colL] = make_float2(v00, v01);
                *(float2*)&dst[r1 * stride + cb + colL] = make_float2(v10, v11);
            }
        }
    }
}

// ============================================================================
// Window attention on mma.sync (unchanged from R11).
// ============================================================================
__global__ __launch_bounds__(64)
void attn_kernel(const __half* __restrict__ q, const __half* __restrict__ k,
                 const __half* __restrict__ v, const float* __restrict__ rpb,
                 __half* __restrict__ out)
{
    __shared__ __half Qs[64][40], Ks[64][40], Vs[64][40];
    __shared__ float rs[225];

    const int hh = blockIdx.x;
    const int wi = blockIdx.y;
    const int tid = threadIdx.x;
    const int lane = tid & 31, warp = tid >> 5;
    const int grp = lane >> 2, thr4 = lane & 3;
    const int b = wi >> 10, rem = wi & 1023;
    const int wh = rem >> 5, ww = rem & 31;
    const int r1 = tid >> 3, c1 = tid & 7;
    const int gh = wh * 8 + r1, gw = ww * 8 + c1;
    const size_t pix = (size_t)(b * 256 + gh) * 256 + gw;
    const int cb = hh * 32;

    for (int i = tid; i < 225; i += 64) rs[i] = rpb[i * 6 + hh];
    {
        const __half* qp = q + pix * 192 + cb;
        const __half* kp = k + pix * 192 + cb;
        const __half* vp = v + pix * 192 + cb;
#pragma unroll
        for (int j = 0; j < 4; j++) {
            *(uint4*)&Qs[tid][j * 8] = *(const uint4*)(qp + j * 8);
            *(uint4*)&Ks[tid][j * 8] = *(const uint4*)(kp + j * 8);
            *(uint4*)&Vs[tid][j * 8] = *(const uint4*)(vp + j * 8);
        }
    }
    __syncthreads();

    const uint32_t qb = smem_u32(&Qs[0][0]) + (lane & 15) * 80 + (lane >> 4) * 16;
    const uint32_t kb = smem_u32(&Ks[0][0]) + (lane & 7) * 80 + ((lane >> 3) & 1) * 16;
    const uint32_t vb = smem_u32(&Vs[0][0]) + (lane & 15) * 80;
    const int mo = warp * 32;

    // ---- S = Q K^T ----
    float sv[2][8][4];
#pragma unroll
    for (int mi = 0; mi < 2; mi++)
#pragma unroll
        for (int ni = 0; ni < 8; ni++)
#pragma unroll
            for (int r = 0; r < 4; r++) sv[mi][ni][r] = 0.0f;
#pragma unroll
    for (int kt = 0; kt < 2; kt++) {
        uint32_t a[2][4], bf[8][2];
#pragma unroll
        for (int mi = 0; mi < 2; mi++)
            LDSM4(a[mi][0], a[mi][1], a[mi][2], a[mi][3],
                  qb + (mo + mi * 16) * 80 + kt * 32);
#pragma unroll
        for (int ni = 0; ni < 8; ni++)
            LDSM2(bf[ni][0], bf[ni][1], kb + ni * 8 * 80 + kt * 32);
#pragma unroll
        for (int mi = 0; mi < 2; mi++)
#pragma unroll
            for (int ni = 0; ni < 8; ni++)
                mma_f16_16x8x16(sv[mi][ni], a[mi], bf[ni]);
    }

    // ---- scale + relative position bias ----
#pragma unroll
    for (int mi = 0; mi < 2; mi++)
#pragma unroll
        for (int ni = 0; ni < 8; ni++)
#pragma unroll
            for (int r = 0; r < 4; r++) {
                int rown = mo + mi * 16 + grp + (r >> 1) * 8;
                int colm = ni * 8 + thr4 * 2 + (r & 1);
                int dr = (rown >> 3) - (colm >> 3) + 7;
                int dc = (rown & 7) - (colm & 7) + 7;
                sv[mi][ni][r] = sv[mi][ni][r] * SCALE + rs[dr * 15 + dc];
            }

    // ---- softmax (rows shared across thr4 quads) ----
    float inv[2][2];
#pragma unroll
    for (int mi = 0; mi < 2; mi++)
#pragma unroll
        for (int hrow = 0; hrow < 2; hrow++) {
            float mx = -1e30f;
#pragma unroll
            for (int ni = 0; ni < 8; ni++) {
                mx = fmaxf(mx, sv[mi][ni][hrow * 2]);
                mx = fmaxf(mx, sv[mi][ni][hrow * 2 + 1]);
            }
            mx = fmaxf(mx, __shfl_xor_sync(0xffffffffu, mx, 1));
            mx = fmaxf(mx, __shfl_xor_sync(0xffffffffu, mx, 2));
            float sum = 0.f;
#pragma unroll
            for (int ni = 0; ni < 8; ni++) {
                float e0 = __expf(sv[mi][ni][hrow * 2] - mx);
                float e1 = __expf(sv[mi][ni][hrow * 2 + 1] - mx);
                sv[mi][ni][hrow * 2] = e0;
                sv[mi][ni][hrow * 2 + 1] = e1;
                sum += e0 + e1;
            }
            sum += __shfl_xor_sync(0xffffffffu, sum, 1);
            sum += __shfl_xor_sync(0xffffffffu, sum, 2);
            inv[mi][hrow] = 1.0f / sum;
        }

    // ---- repack P (fp16) as A fragments ----
    uint32_t pa[2][4][4];
#pragma unroll
    for (int mi = 0; mi < 2; mi++)
#pragma unroll
        for (int kt = 0; kt < 4; kt++) {
            pa[mi][kt][0] = pack_h2(sv[mi][2 * kt][0],     sv[mi][2 * kt][1]);
            pa[mi][kt][1] = pack_h2(sv[mi][2 * kt][2],     sv[mi][2 * kt][3]);
            pa[mi][kt][2] = pack_h2(sv[mi][2 * kt + 1][0], sv[mi][2 * kt + 1][1]);
            pa[mi][kt][3] = pack_h2(sv[mi][2 * kt + 1][2], sv[mi][2 * kt + 1][3]);
        }

    // ---- O = P V ----
    float ov[2][4][4];
#pragma unroll
    for (int mi = 0; mi < 2; mi++)
#pragma unroll
        for (int ni = 0; ni < 4; ni++)
#pragma unroll
            for (int r = 0; r < 4; r++) ov[mi][ni][r] = 0.0f;
#pragma unroll
    for (int kt = 0; kt < 4; kt++) {
        uint32_t bv[4][2];
#pragma unroll
        for (int ni = 0; ni < 4; ni++)
            LDSM2T(bv[ni][0], bv[ni][1], vb + kt * 16 * 80 + ni * 16);
#pragma unroll
        for (int mi = 0; mi < 2; mi++)
#pragma unroll
            for (int ni = 0; ni < 4; ni++)
                mma_f16_16x8x16(ov[mi][ni], pa[mi][kt], bv[ni]);
    }

    // ---- normalize + store (window-ordered pixels) ----
#pragma unroll
    for (int mi = 0; mi < 2; mi++) {
        int rown = mo + mi * 16 + grp;
        size_t o0 = ((size_t)wi * 64 + rown) * 192 + cb + thr4 * 2;
        size_t o1 = o0 + (size_t)8 * 192;
#pragma unroll
        for (int ni = 0; ni < 4; ni++) {
            *(uint32_t*)&out[o0 + ni * 8] =
                pack_h2(ov[mi][ni][0] * inv[mi][0], ov[mi][ni][1] * inv[mi][0]);
            *(uint32_t*)&out[o1 + ni * 8] =
                pack_h2(ov[mi][ni][2] * inv[mi][1], ov[mi][ni][3] * inv[mi][1]);
        }
    }
}

// ============================================================================
extern "C" void kernel_launch(void* const* d_in, const int* in_sizes, int n_in,
                              void* d_out, int out_size)
{
    const float* x      = (const float*)d_in[0];
    const float* v_w    = (const float*)d_in[1];
    const float* v_b    = (const float*)d_in[2];
    const float* qk1_w  = (const float*)d_in[3];
    const float* qk1_b  = (const float*)d_in[4];
    const float* qk3_w1 = (const float*)d_in[5];
    const float* qk3_b1 = (const float*)d_in[6];
    const float* qk3_w2 = (const float*)d_in[7];
    const float* qk3_b2 = (const float*)d_in[8];
    const float* qk3_w3 = (const float*)d_in[9];
    const float* qk3_b3 = (const float*)d_in[10];
    const float* qk5_w1 = (const float*)d_in[11];
    const float* qk5_b1 = (const float*)d_in[12];
    const float* qk5_w2 = (const float*)d_in[13];
    const float* qk5_b2 = (const float*)d_in[14];
    const float* qk5_w3 = (const float*)d_in[15];
    const float* qk5_b3 = (const float*)d_in[16];
    const float* rpb    = (const float*)d_in[17];
    const float* proj_w = (const float*)d_in[18];
    const float* proj_b = (const float*)d_in[19];
    float* out = (float*)d_out;

    __half *xh, *q, *k, *v, *ao, *t3a, *t3b, *t5a, *t5b, *wh;
    cudaGetSymbolAddress((void**)&xh,  g_xh);
    cudaGetSymbolAddress((void**)&q,   g_q);
    cudaGetSymbolAddress((void**)&k,   g_k);
    cudaGetSymbolAddress((void**)&v,   g_v);
    cudaGetSymbolAddress((void**)&ao,  g_ao);
    cudaGetSymbolAddress((void**)&t3a, g_t3a);
    cudaGetSymbolAddress((void**)&t3b, g_t3b);
    cudaGetSymbolAddress((void**)&t5a, g_t5a);
    cudaGetSymbolAddress((void**)&t5b, g_t5b);
    cudaGetSymbolAddress((void**)&wh,  g_wh);

    // packed weight offsets (halves), order matches pack_all tables
    const int O_V = 0, O_Q1 = 36864, O_3W1 = 61440, O_3W2 = 116736,
              O_3W3 = 117760, O_5W1 = 154624, O_5W2 = 231424, O_5W3 = 231680,
              O_PJ = 282880;

    const int G1_SMEM = G1_AB + 4 * G1_BB;   // 114688
    cudaFuncSetAttribute(gemm1<3, 192, false, __half>,
                         cudaFuncAttributeMaxDynamicSharedMemorySize, G1_SMEM);
    cudaFuncSetAttribute(gemm1<2, 128, true, __half>,
                         cudaFuncAttributeMaxDynamicSharedMemorySize, G1_SMEM);
    cudaFuncSetAttribute(gemm1<3, 192, false, float>,
                         cudaFuncAttributeMaxDynamicSharedMemorySize, G1_SMEM);

    // prepasses
    f2h_kernel<<<NPIX * CDIM / (256 * 8), 256>>>(x, xh);
    PackSrc ps;
    ps.p[0] = v_w;    ps.p[1] = qk1_w;  ps.p[2] = qk3_w1;
    ps.p[3] = qk3_w2; ps.p[4] = qk3_w3; ps.p[5] = qk5_w1;
    ps.p[6] = qk5_w2; ps.p[7] = qk5_w3; ps.p[8] = proj_w;
    pack_all<<<(319744 + 255) / 256, 256>>>(ps, wh);

    // v = conv1x1(x): A-resident GEMM, 3 n-blocks per CTA
    gemm1<3, 192, false, __half><<<1024, 256, G1_SMEM>>>(
        xh, wh + O_V, v_b, v, nullptr);
    // qk1: A-resident GEMM, 2 n-blocks (q, k)
    gemm1<2, 128, true, __half><<<1024, 256, G1_SMEM>>>(
        xh, wh + O_Q1, qk1_b, q, k);
    // scale-3 branch
    conv_mma<3, 192, 32, 32, 32, true, false, __half, 128>
        <<<dim3(1024, 1), 128>>>(xh, wh + O_3W1, qk3_b1, t3a, nullptr, 0);
    conv_mma<1, 32, 32, 32, 32, true, false, __half, 128>
        <<<dim3(1024, 1), 128>>>(t3a, wh + O_3W2, qk3_b2, t3b, nullptr, 0);
    conv_mma<3, 32, 128, 64, 192, false, true, __half, 256>
        <<<dim3(1024, 2), 256>>>(t3b, wh + O_3W3, qk3_b3, q, k, 64);
    // scale-5 branch
    conv_mma<5, 192, 16, 16, 16, true, false, __half, 128>
        <<<dim3(1024, 1), 128>>>(xh, wh + O_5W1, qk5_b1, t5a, nullptr, 0);
    conv_mma<1, 16, 16, 16, 16, true, false, __half, 128>
        <<<dim3(1024, 1), 128>>>(t5a, wh + O_5W2, qk5_b2, t5b, nullptr, 0);
    conv_mma<5, 16, 128, 32, 192, false, true, __half, 128>
        <<<dim3(1024, 4), 128>>>(t5b, wh + O_5W3, qk5_b3, q, k, 128);
    // window attention (mma, fp16 in/out)
    attn_kernel<<<dim3(6, 4096), 64>>>(q, k, v, rpb, ao);
    // output projection: A-resident GEMM straight into d_out (fp32)
    gemm1<3, 192, false, float><<<1024, 256, G1_SMEM>>>(
        ao, wh + O_PJ, proj_b, out, nullptr);
}

// round 16
// speedup vs baseline: 1.2268x; 1.0049x over previous
#include <cuda_runtime.h>
#include <cuda_fp16.h>
#include <cstdint>

#define NPIX (4 * 256 * 256)   // 262144 pixels
#define CDIM 192
#define SCALE 0.17677669529663689f

// ---------------- scratch (static device arrays; no runtime allocs) --------
__device__ __half g_xh [NPIX * CDIM];
__device__ __half g_q  [NPIX * CDIM];
__device__ __half g_k  [NPIX * CDIM];
__device__ __half g_v  [NPIX * CDIM];
__device__ __half g_ao [NPIX * CDIM];
__device__ __half g_t3a[NPIX * 32];
__device__ __half g_t3b[NPIX * 32];
__device__ __half g_t5a[NPIX * 16];
__device__ __half g_t5b[NPIX * 16];
__device__ __half g_wh [319744];       // packed fp16 weights (incl. proj)

__device__ __forceinline__ uint32_t pack_h2(float a, float b) {
    __half2 h = __floats2half2_rn(a, b);
    return *(uint32_t*)&h;
}
__device__ __forceinline__ uint32_t smem_u32(const void* p) {
    uint32_t a;
    asm("{ .reg .u64 t; cvta.to.shared.u64 t, %1; cvt.u32.u64 %0, t; }"
        : "=r"(a) : "l"(p));
    return a;
}
__device__ __forceinline__ void cpa16(uint32_t dst, const void* src, int nbytes) {
    asm volatile("cp.async.cg.shared.global [%0], [%1], 16, %2;"
                 :: "r"(dst), "l"(src), "r"(nbytes));
}
__device__ __forceinline__ void cpa_commit() {
    asm volatile("cp.async.commit_group;" ::: "memory");
}
template <int N>
__device__ __forceinline__ void cpa_wait() {
    asm volatile("cp.async.wait_group %0;" :: "n"(N) : "memory");
}
__device__ __forceinline__ void mma_f16_16x8x16(float* c, const uint32_t* a,
                                                const uint32_t* b) {
    asm volatile(
        "mma.sync.aligned.m16n8k16.row.col.f32.f16.f16.f32 "
        "{%0,%1,%2,%3}, {%4,%5,%6,%7}, {%8,%9}, {%0,%1,%2,%3};"
        : "+f"(c[0]), "+f"(c[1]), "+f"(c[2]), "+f"(c[3])
        : "r"(a[0]), "r"(a[1]), "r"(a[2]), "r"(a[3]), "r"(b[0]), "r"(b[1]));
}
#define LDSM4(r0, r1, r2, r3, addr)                                           \
    asm volatile("ldmatrix.sync.aligned.m8n8.x4.shared.b16 {%0,%1,%2,%3}, [%4];" \
                 : "=r"(r0), "=r"(r1), "=r"(r2), "=r"(r3) : "r"(addr))
#define LDSM2(r0, r1, addr)                                                   \
    asm volatile("ldmatrix.sync.aligned.m8n8.x2.shared.b16 {%0,%1}, [%2];"    \
                 : "=r"(r0), "=r"(r1) : "r"(addr))
#define LDSM2T(r0, r1, addr)                                                  \
    asm volatile("ldmatrix.sync.aligned.m8n8.x2.trans.shared.b16 {%0,%1}, [%2];" \
                 : "=r"(r0), "=r"(r1) : "r"(addr))

// ---------------- prepasses -------------------------------------------------
__global__ __launch_bounds__(256)
void f2h_kernel(const float* __restrict__ in, __half* __restrict__ out)
{
    int i = blockIdx.x * blockDim.x + threadIdx.x;   // one uint4 (8 halves)
    float4 a = ((const float4*)in)[2 * i];
    float4 b = ((const float4*)in)[2 * i + 1];
    uint4 o;
    o.x = pack_h2(a.x, a.y); o.y = pack_h2(a.z, a.w);
    o.z = pack_h2(b.x, b.y); o.w = pack_h2(b.z, b.w);
    ((uint4*)out)[i] = o;
}

// Pack ALL OIHW fp32 weights -> fp16. Entries 0 (v) and 1 (qk1) are merged
// into one [cc][320 couts][16ch] layout (v couts 0-191, qk1 couts 192-319)
// occupying halves [0, 61440). All other entries keep the sequential
// [kh][cc][kw][cout][16ch] layout at their original offsets.
struct PackSrc { const float* p[9]; };
__global__ __launch_bounds__(256)
void pack_all(PackSrc ps, __half* __restrict__ dst)
{
    const int KSt[9]  = {1, 1, 3, 1, 3, 5, 1, 5, 1};
    const int CINt[9] = {192, 192, 192, 32, 32, 192, 16, 16, 192};
    const int COUTt[9]= {192, 128, 32, 32, 128, 16, 16, 128, 192};
    const int TOTt[9] = {36864, 24576, 55296, 1024, 36864, 76800, 256, 51200, 36864};
    int idx = blockIdx.x * 256 + threadIdx.x;
    if (idx >= 319744) return;
    int w = 0, local = idx;
    while (local >= TOTt[w]) { local -= TOTt[w]; w++; }
    const int KS = KSt[w], CIN = CINt[w], COUT = COUTt[w];
    int ci = local & 15;
    int t = local >> 4;
    int cout = t % COUT; t /= COUT;
    int kw = t % KS; t /= KS;
    int cc = t % (CIN / 16); t /= (CIN / 16);
    int kh = t;
    float val = ps.p[w][((size_t)(cout * CIN + cc * 16 + ci) * KS + kh) * KS + kw];
    int di;
    if (w == 0)      di = cc * (320 * 16) + cout * 16 + ci;
    else if (w == 1) di = cc * (320 * 16) + (192 + cout) * 16 + ci;
    else             di = idx;
    dst[di] = __float2half(val);
}

// ============================================================================
// gemm1: 1x1 conv with CIN=192, A tile fully SMEM-resident, 4-deep B ring.
// One CTA = 256 pixels (one image row) x NBLK n-blocks of 64 couts.
// MODE 0: all n-blocks -> out0 at cb = nb*64, bias0.
// MODE 1 (fused v+qk1): nb 0-2 -> out0 (v, cb=nb*64, bias0);
//                       nb 3 -> out1 (q, cb=0, bias1);
//                       nb 4 -> out2 (k, cb=0, bias1+64).
// grid = 1024. SMEM = 256*400 + 4*3072 = 114688 B (dynamic).
// ============================================================================
#define G1_AS 400                      // A row stride bytes (100 words, %32==4)
#define G1_AB (256 * G1_AS)            // 102400
#define G1_BB 3072                     // one B buffer (64 couts * 48B)

template <int NBLK, int CT, int MODE, typename OutT>
__global__ __launch_bounds__(256)
void gemm1(const __half* __restrict__ X, const __half* __restrict__ Wp,
           const float* __restrict__ bias0, const float* __restrict__ bias1,
           OutT* __restrict__ out0, OutT* __restrict__ out1,
           OutT* __restrict__ out2)
{
    constexpr int NCHUNK = NBLK * 12;
    extern __shared__ __align__(16) char smem[];
    const int tid = threadIdx.x;
    const int lane = tid & 31, warp = tid >> 5;
    const int grp = lane >> 2, thr4 = lane & 3;
    const int mo = (warp >> 1) * 64;         // warp M offset (MI=4 -> 64 rows)
    const int no = (warp & 1) * 32;          // warp N offset (NI=4 -> 32 cols)
    const int pix0 = blockIdx.x << 8;        // full image row
    const uint32_t smbase = smem_u32(smem);

    // issue B loads for global chunk g into ring buffer g%4 (NO commit inside)
    auto issueB = [&](int g) {
        const int nb = g / 12, c = g - nb * 12;
        if (tid < 128) {
            const int j = tid >> 1, hi = tid & 1;
            cpa16(smbase + G1_AB + (g & 3) * G1_BB + j * 48 + hi * 16,
                  Wp + (size_t)c * (CT * 16) + (nb * 64 + j) * 16 + hi * 8, 16);
        }
    };

    // ---- prologue: A (96KB) + B0 in group 0; B1, B2 in groups 1, 2 ----
#pragma unroll
    for (int r = 0; r < 24; r++) {
        const int i = tid + r * 256;         // 0..6143 16B-chunks
        const int pixel = i / 24, ch = i - pixel * 24;
        cpa16(smbase + pixel * G1_AS + ch * 16,
              X + (size_t)pix0 * 192 + (size_t)i * 8, 16);
    }
    issueB(0);
    cpa_commit();                            // group: A + B0
    issueB(1); cpa_commit();
    if (NCHUNK > 2) issueB(2);
    cpa_commit();

    const uint32_t aF = smbase + (lane & 15) * G1_AS + (lane >> 4) * 16;
    const uint32_t bF = smbase + G1_AB + (lane & 7) * 48 + ((lane >> 3) & 1) * 16;

    float acc[4][4][4];
#pragma unroll
    for (int i = 0; i < 4; i++)
#pragma unroll
        for (int j = 0; j < 4; j++)
#pragma unroll
            for (int r = 0; r < 4; r++) acc[i][j][r] = 0.0f;

#pragma unroll 1
    for (int g = 0; g < NCHUNK; g++) {
        const int nb = g / 12, c = g - nb * 12;
        cpa_wait<2>();                       // B_g complete (B_{g+1},B_{g+2} pending)
        __syncthreads();                     // B_g visible; buffer (g-1)%4 drained
        if (g + 3 < NCHUNK) issueB(g + 3);
        cpa_commit();                        // keep group count exact
        {
            uint32_t a[4][4], b[4][2];
#pragma unroll
            for (int mi = 0; mi < 4; mi++)
                LDSM4(a[mi][0], a[mi][1], a[mi][2], a[mi][3],
                      aF + (mo + mi * 16) * G1_AS + c * 32);
#pragma unroll
            for (int ni = 0; ni < 4; ni++)
                LDSM2(b[ni][0], b[ni][1],
                      bF + (g & 3) * G1_BB + (no + ni * 8) * 48);
#pragma unroll
            for (int mi = 0; mi < 4; mi++)
#pragma unroll
                for (int ni = 0; ni < 4; ni++)
                    mma_f16_16x8x16(acc[mi][ni], a[mi], b[ni]);
        }

        if (c == 11) {
            // ---- epilogue for n-block nb, then reset accumulators ----
            OutT* dst;
            int cb;
            const float* bptr;
            if (MODE == 1) {
                if (nb < 3)      { dst = out0; cb = nb * 64; bptr = bias0 + nb * 64; }
                else if (nb == 3){ dst = out1; cb = 0;       bptr = bias1; }
                else             { dst = out2; cb = 0;       bptr = bias1 + 64; }
            } else {
                dst = out0; cb = nb * 64; bptr = bias0 + nb * 64;
            }
#pragma unroll
            for (int mi = 0; mi < 4; mi++) {
                size_t r0 = (size_t)(pix0 + mo + mi * 16 + grp);
                size_t r1 = r0 + 8;
#pragma unroll
                for (int ni = 0; ni < 4; ni++) {
                    int colL = no + ni * 8 + 2 * thr4;
                    float b0 = __ldg(&bptr[colL]);
                    float b1 = __ldg(&bptr[colL + 1]);
                    float v00 = acc[mi][ni][0] + b0, v01 = acc[mi][ni][1] + b1;
                    float v10 = acc[mi][ni][2] + b0, v11 = acc[mi][ni][3] + b1;
                    if (sizeof(OutT) == 2) {
                        *(uint32_t*)&dst[r0 * 192 + cb + colL] = pack_h2(v00, v01);
                        *(uint32_t*)&dst[r1 * 192 + cb + colL] = pack_h2(v10, v11);
                    } else {
                        *(float2*)&dst[r0 * 192 + cb + colL] = make_float2(v00, v01);
                        *(float2*)&dst[r1 * 192 + cb + colL] = make_float2(v10, v11);
                    }
                    acc[mi][ni][0] = 0.f; acc[mi][ni][1] = 0.f;
                    acc[mi][ni][2] = 0.f; acc[mi][ni][3] = 0.f;
                }
            }
        }
    }
}

// ============================================================================
// Implicit-GEMM conv (R11 config): fp16 mma.sync, cp.async double buffer,
// ldmatrix fragments. One CTA = one image row (256 pixels) x BN couts.
// ============================================================================
template <int KS, int CIN, int CT, int BN, int OSTR, bool RELU, bool SPLIT,
          typename OutT, int NT>
__global__ __launch_bounds__(NT)
void conv_mma(const __half* __restrict__ X, const __half* __restrict__ Wp,
              const float* __restrict__ bias, OutT* __restrict__ out0,
              OutT* __restrict__ out1, int cbase)
{
    constexpr int PAD = KS / 2;
    constexpr int NCH = CIN / 16;
    constexpr int NSTAGE = KS * NCH;
    constexpr int SLAB = 256 + 2 * PAD;
    constexpr int ABYTES = SLAB * 48;
    constexpr int BBYTES = KS * BN * 48;
    constexpr int BUFB = ABYTES + BBYTES;
    __shared__ alignas(16) char smem[2 * BUFB];

    const int tid = threadIdx.x;
    const int lane = tid & 31, warp = tid >> 5;
    const int grp = lane >> 2, thr4 = lane & 3;

    constexpr int NWARPS = NT / 32;
    constexpr int NW = (BN == 64) ? 2 : 1;
    constexpr int MW = NWARPS / NW;
    constexpr int WROWS = 256 / MW;          // 64
    constexpr int WCOLS = BN / NW;
    constexpr int MI = WROWS / 16;           // 4
    constexpr int NI = WCOLS / 8;
    static_assert(MI == 4, "tiling");
    const int mo = (NW == 2 ? (warp >> 1) : warp) * WROWS;
    const int no = (NW == 2 ? (warp & 1) : 0) * WCOLS;

    const int row = blockIdx.x;              // b*256 + h
    const int h = row & 255;
    const int pixbase = row << 8;
    const int n0 = blockIdx.y * BN;
    const uint32_t smbase = smem_u32(smem);

    float acc[MI][NI][4];
#pragma unroll
    for (int i = 0; i < MI; i++)
#pragma unroll
        for (int j = 0; j < NI; j++)
#pragma unroll
            for (int r = 0; r < 4; r++) acc[i][j][r] = 0.0f;

    auto issue = [&](int s) {
        const int kh = s / NCH;
        const int cc = s - kh * NCH;
        const int c0 = cc * 16;
        const int hs = h + kh - PAD;
        const bool vh = ((unsigned)hs < 256u);
        const int spix = (row - h + hs) << 8;
        const uint32_t aoff = smbase + (s & 1) * BUFB;
        for (int i = tid; i < SLAB * 2; i += NT) {
            const int p = i >> 1, hi = i & 1;
            const int ws = p - PAD;
            const bool ok = vh && ((unsigned)ws < 256u);
            const __half* src = ok
                ? X + ((size_t)(spix + ws) * CIN + c0 + hi * 8) : X;
            cpa16(aoff + p * 48 + hi * 16, src, ok ? 16 : 0);
        }
        const uint32_t boff = aoff + ABYTES;
        const __half* wb = Wp + (size_t)(kh * NCH + cc) * KS * CT * 16;
        for (int i = tid; i < KS * BN * 2; i += NT) {
            const int r = i >> 1, hi = i & 1;
            const int kw = r / BN, j = r - kw * BN;
            cpa16(boff + r * 48 + hi * 16,
                  wb + ((size_t)kw * CT + n0 + j) * 16 + hi * 8, 16);
        }
        cpa_commit();
    };

    auto compute = [&](int buf) {
        const uint32_t aB = smbase + buf * BUFB
                            + (lane & 15) * 48 + (lane >> 4) * 16;
        const uint32_t bB = smbase + buf * BUFB + ABYTES
                            + (lane & 7) * 48 + ((lane >> 3) & 1) * 16;
#pragma unroll
        for (int kw = 0; kw < KS; kw++) {
            uint32_t a[MI][4], b[NI][2];
#pragma unroll
            for (int mi = 0; mi < MI; mi++)
                LDSM4(a[mi][0], a[mi][1], a[mi][2], a[mi][3],
                      aB + (mo + mi * 16 + kw) * 48);
#pragma unroll
            for (int ni = 0; ni < NI; ni++)
                LDSM2(b[ni][0], b[ni][1], bB + (kw * BN + no + ni * 8) * 48);
#pragma unroll
            for (int mi = 0; mi < MI; mi++)
#pragma unroll
                for (int ni = 0; ni < NI; ni++)
                    mma_f16_16x8x16(acc[mi][ni], a[mi], b[ni]);
        }
    };

    issue(0);
#pragma unroll 1
    for (int s = 0; s < NSTAGE; s++) {
        if (s + 1 < NSTAGE) { issue(s + 1); cpa_wait<1>(); }
        else                { cpa_wait<0>(); }
        __syncthreads();
        compute(s & 1);
        __syncthreads();
    }

    // ---- epilogue ----
    OutT* dst;
    int cb, stride;
    if (SPLIT) {
        if (n0 < 64) { dst = out0; cb = cbase + n0; }
        else         { dst = out1; cb = cbase + n0 - 64; }
        stride = 192;
    } else { dst = out0; cb = n0; stride = OSTR; }

#pragma unroll
    for (int mi = 0; mi < MI; mi++) {
        size_t r0 = (size_t)(pixbase + mo + mi * 16 + grp);
        size_t r1 = r0 + 8;
#pragma unroll
        for (int ni = 0; ni < NI; ni++) {
            int colL = no + ni * 8 + 2 * thr4;
            float b0 = __ldg(&bias[n0 + colL]);
            float b1 = __ldg(&bias[n0 + colL + 1]);
            float v00 = acc[mi][ni][0] + b0, v01 = acc[mi][ni][1] + b1;
            float v10 = acc[mi][ni][2] + b0, v11 = acc[mi][ni][3] + b1;
            if (RELU) {
                v00 = v00 >= 0.f ? v00 : 0.2f * v00;
                v01 = v01 >= 0.f ? v01 : 0.2f * v01;
                v10 = v10 >= 0.f ? v10 : 0.2f * v10;
                v11 = v11 >= 0.f ? v11 : 0.2f * v11;
            }
            if (sizeof(OutT) == 2) {
                *(uint32_t*)&dst[r0 * stride + cb + colL] = pack_h2(v00, v01);
                *(uint32_t*)&dst[r1 * stride + cb + colL] = pack_h2(v10, v11);
            } else {
                *(float2*)&dst[r0 * stride + cb + colL] = make_float2(v00, v01);
                *(float2*)&dst[r1 * stride + cb + colL] = make_float2(v10, v11);
            }
        }
    }
}

// ============================================================================
// Window attention on mma.sync (unchanged from R11).
// ============================================================================
__global__ __launch_bounds__(64)
void attn_kernel(const __half* __restrict__ q, const __half* __restrict__ k,
                 const __half* __restrict__ v, const float* __restrict__ rpb,
                 __half* __restrict__ out)
{
    __shared__ __half Qs[64][40], Ks[64][40], Vs[64][40];
    __shared__ float rs[225];

    const int hh = blockIdx.x;
    const int wi = blockIdx.y;
    const int tid = threadIdx.x;
    const int lane = tid & 31, warp = tid >> 5;
    const int grp = lane >> 2, thr4 = lane & 3;
    const int b = wi >> 10, rem = wi & 1023;
    const int wh = rem >> 5, ww = rem & 31;
    const int r1 = tid >> 3, c1 = tid & 7;
    const int gh = wh * 8 + r1, gw = ww * 8 + c1;
    const size_t pix = (size_t)(b * 256 + gh) * 256 + gw;
    const int cb = hh * 32;

    for (int i = tid; i < 225; i += 64) rs[i] = rpb[i * 6 + hh];
    {
        const __half* qp = q + pix * 192 + cb;
        const __half* kp = k + pix * 192 + cb;
        const __half* vp = v + pix * 192 + cb;
#pragma unroll
        for (int j = 0; j < 4; j++) {
            *(uint4*)&Qs[tid][j * 8] = *(const uint4*)(qp + j * 8);
            *(uint4*)&Ks[tid][j * 8] = *(const uint4*)(kp + j * 8);
            *(uint4*)&Vs[tid][j * 8] = *(const uint4*)(vp + j * 8);
        }
    }
    __syncthreads();

    const uint32_t qb = smem_u32(&Qs[0][0]) + (lane & 15) * 80 + (lane >> 4) * 16;
    const uint32_t kb = smem_u32(&Ks[0][0]) + (lane & 7) * 80 + ((lane >> 3) & 1) * 16;
    const uint32_t vb = smem_u32(&Vs[0][0]) + (lane & 15) * 80;
    const int mo = warp * 32;

    // ---- S = Q K^T ----
    float sv[2][8][4];
#pragma unroll
    for (int mi = 0; mi < 2; mi++)
#pragma unroll
        for (int ni = 0; ni < 8; ni++)
#pragma unroll
            for (int r = 0; r < 4; r++) sv[mi][ni][r] = 0.0f;
#pragma unroll
    for (int kt = 0; kt < 2; kt++) {
        uint32_t a[2][4], bf[8][2];
#pragma unroll
        for (int mi = 0; mi < 2; mi++)
            LDSM4(a[mi][0], a[mi][1], a[mi][2], a[mi][3],
                  qb + (mo + mi * 16) * 80 + kt * 32);
#pragma unroll
        for (int ni = 0; ni < 8; ni++)
            LDSM2(bf[ni][0], bf[ni][1], kb + ni * 8 * 80 + kt * 32);
#pragma unroll
        for (int mi = 0; mi < 2; mi++)
#pragma unroll
            for (int ni = 0; ni < 8; ni++)
                mma_f16_16x8x16(sv[mi][ni], a[mi], bf[ni]);
    }

    // ---- scale + relative position bias ----
#pragma unroll
    for (int mi = 0; mi < 2; mi++)
#pragma unroll
        for (int ni = 0; ni < 8; ni++)
#pragma unroll
            for (int r = 0; r < 4; r++) {
                int rown = mo + mi * 16 + grp + (r >> 1) * 8;
                int colm = ni * 8 + thr4 * 2 + (r & 1);
                int dr = (rown >> 3) - (colm >> 3) + 7;
                int dc = (rown & 7) - (colm & 7) + 7;
                sv[mi][ni][r] = sv[mi][ni][r] * SCALE + rs[dr * 15 + dc];
            }

    // ---- softmax (rows shared across thr4 quads) ----
    float inv[2][2];
#pragma unroll
    for (int mi = 0; mi < 2; mi++)
#pragma unroll
        for (int hrow = 0; hrow < 2; hrow++) {
            float mx = -1e30f;
#pragma unroll
            for (int ni = 0; ni < 8; ni++) {
                mx = fmaxf(mx, sv[mi][ni][hrow * 2]);
                mx = fmaxf(mx, sv[mi][ni][hrow * 2 + 1]);
            }
            mx = fmaxf(mx, __shfl_xor_sync(0xffffffffu, mx, 1));
            mx = fmaxf(mx, __shfl_xor_sync(0xffffffffu, mx, 2));
            float sum = 0.f;
#pragma unroll
            for (int ni = 0; ni < 8; ni++) {
                float e0 = __expf(sv[mi][ni][hrow * 2] - mx);
                float e1 = __expf(sv[mi][ni][hrow * 2 + 1] - mx);
                sv[mi][ni][hrow * 2] = e0;
                sv[mi][ni][hrow * 2 + 1] = e1;
                sum += e0 + e1;
            }
            sum += __shfl_xor_sync(0xffffffffu, sum, 1);
            sum += __shfl_xor_sync(0xffffffffu, sum, 2);
            inv[mi][hrow] = 1.0f / sum;
        }

    // ---- repack P (fp16) as A fragments ----
    uint32_t pa[2][4][4];
#pragma unroll
    for (int mi = 0; mi < 2; mi++)
#pragma unroll
        for (int kt = 0; kt < 4; kt++) {
            pa[mi][kt][0] = pack_h2(sv[mi][2 * kt][0],     sv[mi][2 * kt][1]);
            pa[mi][kt][1] = pack_h2(sv[mi][2 * kt][2],     sv[mi][2 * kt][3]);
            pa[mi][kt][2] = pack_h2(sv[mi][2 * kt + 1][0], sv[mi][2 * kt + 1][1]);
            pa[mi][kt][3] = pack_h2(sv[mi][2 * kt + 1][2], sv[mi][2 * kt + 1][3]);
        }

    // ---- O = P V ----
    float ov[2][4][4];
#pragma unroll
    for (int mi = 0; mi < 2; mi++)
#pragma unroll
        for (int ni = 0; ni < 4; ni++)
#pragma unroll
            for (int r = 0; r < 4; r++) ov[mi][ni][r] = 0.0f;
#pragma unroll
    for (int kt = 0; kt < 4; kt++) {
        uint32_t bv[4][2];
#pragma unroll
        for (int ni = 0; ni < 4; ni++)
            LDSM2T(bv[ni][0], bv[ni][1], vb + kt * 16 * 80 + ni * 16);
#pragma unroll
        for (int mi = 0; mi < 2; mi++)
#pragma unroll
            for (int ni = 0; ni < 4; ni++)
                mma_f16_16x8x16(ov[mi][ni], pa[mi][kt], bv[ni]);
    }

    // ---- normalize + store (window-ordered pixels) ----
#pragma unroll
    for (int mi = 0; mi < 2; mi++) {
        int rown = mo + mi * 16 + grp;
        size_t o0 = ((size_t)wi * 64 + rown) * 192 + cb + thr4 * 2;
        size_t o1 = o0 + (size_t)8 * 192;
#pragma unroll
        for (int ni = 0; ni < 4; ni++) {
            *(uint32_t*)&out[o0 + ni * 8] =
                pack_h2(ov[mi][ni][0] * inv[mi][0], ov[mi][ni][1] * inv[mi][0]);
            *(uint32_t*)&out[o1 + ni * 8] =
                pack_h2(ov[mi][ni][2] * inv[mi][1], ov[mi][ni][3] * inv[mi][1]);
        }
    }
}

// ============================================================================
extern "C" void kernel_launch(void* const* d_in, const int* in_sizes, int n_in,
                              void* d_out, int out_size)
{
    const float* x      = (const float*)d_in[0];
    const float* v_w    = (const float*)d_in[1];
    const float* v_b    = (const float*)d_in[2];
    const float* qk1_w  = (const float*)d_in[3];
    const float* qk1_b  = (const float*)d_in[4];
    const float* qk3_w1 = (const float*)d_in[5];
    const float* qk3_b1 = (const float*)d_in[6];
    const float* qk3_w2 = (const float*)d_in[7];
    const float* qk3_b2 = (const float*)d_in[8];
    const float* qk3_w3 = (const float*)d_in[9];
    const float* qk3_b3 = (const float*)d_in[10];
    const float* qk5_w1 = (const float*)d_in[11];
    const float* qk5_b1 = (const float*)d_in[12];
    const float* qk5_w2 = (const float*)d_in[13];
    const float* qk5_b2 = (const float*)d_in[14];
    const float* qk5_w3 = (const float*)d_in[15];
    const float* qk5_b3 = (const float*)d_in[16];
    const float* rpb    = (const float*)d_in[17];
    const float* proj_w = (const float*)d_in[18];
    const float* proj_b = (const float*)d_in[19];
    float* out = (float*)d_out;

    __half *xh, *q, *k, *v, *ao, *t3a, *t3b, *t5a, *t5b, *wh;
    cudaGetSymbolAddress((void**)&xh,  g_xh);
    cudaGetSymbolAddress((void**)&q,   g_q);
    cudaGetSymbolAddress((void**)&k,   g_k);
    cudaGetSymbolAddress((void**)&v,   g_v);
    cudaGetSymbolAddress((void**)&ao,  g_ao);
    cudaGetSymbolAddress((void**)&t3a, g_t3a);
    cudaGetSymbolAddress((void**)&t3b, g_t3b);
    cudaGetSymbolAddress((void**)&t5a, g_t5a);
    cudaGetSymbolAddress((void**)&t5b, g_t5b);
    cudaGetSymbolAddress((void**)&wh,  g_wh);

    // packed weight offsets (halves): [0,61440) = merged v+qk1 (CT=320)
    const int O_VQ = 0, O_3W1 = 61440, O_3W2 = 116736,
              O_3W3 = 117760, O_5W1 = 154624, O_5W2 = 231424, O_5W3 = 231680,
              O_PJ = 282880;

    const int G1_SMEM = G1_AB + 4 * G1_BB;   // 114688
    cudaFuncSetAttribute(gemm1<5, 320, 1, __half>,
                         cudaFuncAttributeMaxDynamicSharedMemorySize, G1_SMEM);
    cudaFuncSetAttribute(gemm1<3, 192, 0, float>,
                         cudaFuncAttributeMaxDynamicSharedMemorySize, G1_SMEM);

    // prepasses
    f2h_kernel<<<NPIX * CDIM / (256 * 8), 256>>>(x, xh);
    PackSrc ps;
    ps.p[0] = v_w;    ps.p[1] = qk1_w;  ps.p[2] = qk3_w1;
    ps.p[3] = qk3_w2; ps.p[4] = qk3_w3; ps.p[5] = qk5_w1;
    ps.p[6] = qk5_w2; ps.p[7] = qk5_w3; ps.p[8] = proj_w;
    pack_all<<<(319744 + 255) / 256, 256>>>(ps, wh);

    // fused v + qk1: one A pass, 5 n-blocks (v0,v1,v2,q,k)
    gemm1<5, 320, 1, __half><<<1024, 256, G1_SMEM>>>(
        xh, wh + O_VQ, v_b, qk1_b, v, q, k);
    // scale-3 branch
    conv_mma<3, 192, 32, 32, 32, true, false, __half, 128>
        <<<dim3(1024, 1), 128>>>(xh, wh + O_3W1, qk3_b1, t3a, nullptr, 0);
    conv_mma<1, 32, 32, 32, 32, true, false, __half, 128>
        <<<dim3(1024, 1), 128>>>(t3a, wh + O_3W2, qk3_b2, t3b, nullptr, 0);
    conv_mma<3, 32, 128, 64, 192, false, true, __half, 256>
        <<<dim3(1024, 2), 256>>>(t3b, wh + O_3W3, qk3_b3, q, k, 64);
    // scale-5 branch
    conv_mma<5, 192, 16, 16, 16, true, false, __half, 128>
        <<<dim3(1024, 1), 128>>>(xh, wh + O_5W1, qk5_b1, t5a, nullptr, 0);
    conv_mma<1, 16, 16, 16, 16, true, false, __half, 128>
        <<<dim3(1024, 1), 128>>>(t5a, wh + O_5W2, qk5_b2, t5b, nullptr, 0);
    conv_mma<5, 16, 128, 32, 192, false, true, __half, 128>
        <<<dim3(1024, 4), 128>>>(t5b, wh + O_5W3, qk5_b3, q, k, 128);
    // window attention (mma, fp16 in/out)
    attn_kernel<<<dim3(6, 4096), 64>>>(q, k, v, rpb, ao);
    // output projection: A-resident GEMM straight into d_out (fp32)
    gemm1<3, 192, 0, float><<<1024, 256, G1_SMEM>>>(
        ao, wh + O_PJ, proj_b, nullptr, out, nullptr, nullptr);
}